// round 13
// baseline (speedup 1.0000x reference)
#include <cuda_runtime.h>
#include <cuda_fp16.h>
#include <math.h>
#include <stdint.h>

#define T_TOK     8192
#define DMODEL    1024
#define DFF       4096
#define E_ROUTED  7
#define TOPK      2
#define CAPACITY  2926
#define WPER      ((size_t)DMODEL * DFF)

// ---------------- scratch ----------------
__device__ __half g_ht[(size_t)T_TOK * DMODEL];
__device__ int    g_topidx[T_TOK * TOPK];
__device__ float  g_gate[T_TOK * TOPK];
__device__ int    g_pos[TOPK * T_TOK];
__device__ int    g_slot_token[E_ROUTED * CAPACITY];
__device__ int    g_count[E_ROUTED];
__device__ __half g_w1t[8 * WPER];                       // [e][F][D] K-major fp16
__device__ __half g_w3t[8 * WPER];
__device__ __half g_w2t[8 * WPER];                       // [e][D][F] K-major fp16
__device__ __half g_ub [(size_t)E_ROUTED * CAPACITY * DFF];
__device__ __half g_ubs[(size_t)T_TOK * DFF];
__device__ float  g_ye [(size_t)E_ROUTED * CAPACITY * DMODEL];
__device__ float  g_ys [(size_t)T_TOK * DMODEL];

// ---------------- helpers ----------------
__device__ __forceinline__ uint32_t smem_u32(const void* p) {
    return (uint32_t)__cvta_generic_to_shared(p);
}
__device__ __forceinline__ void cp16(uint32_t d, const void* s) {
    asm volatile("cp.async.cg.shared.global [%0], [%1], 16;" :: "r"(d), "l"(s) : "memory");
}
__device__ __forceinline__ void cp_commit() {
    asm volatile("cp.async.commit_group;" ::: "memory");
}
template <int N>
__device__ __forceinline__ void cp_wait() {
    asm volatile("cp.async.wait_group %0;" :: "n"(N) : "memory");
}
__device__ __forceinline__ void ldsm_x4(uint32_t& r0, uint32_t& r1, uint32_t& r2,
                                        uint32_t& r3, uint32_t addr) {
    asm volatile("ldmatrix.sync.aligned.m8n8.x4.shared.b16 {%0,%1,%2,%3}, [%4];"
                 : "=r"(r0), "=r"(r1), "=r"(r2), "=r"(r3) : "r"(addr));
}
__device__ __forceinline__ void mma_f16(float c[4], uint32_t a0, uint32_t a1,
                                        uint32_t a2, uint32_t a3,
                                        uint32_t b0, uint32_t b1) {
    asm volatile(
        "mma.sync.aligned.m16n8k16.row.col.f32.f16.f16.f32 "
        "{%0,%1,%2,%3},{%4,%5,%6,%7},{%8,%9},{%0,%1,%2,%3};"
        : "+f"(c[0]), "+f"(c[1]), "+f"(c[2]), "+f"(c[3])
        : "r"(a0), "r"(a1), "r"(a2), "r"(a3), "r"(b0), "r"(b1));
}
__device__ __forceinline__ float silu_f(float v) { return v / (1.0f + __expf(-v)); }

// ---------------- 0) Fused LayerNorm + Router ----------------
__device__ __forceinline__ float blockReduceSum256(float v, float* sh8) {
    int lane = threadIdx.x & 31, wid = threadIdx.x >> 5;
    #pragma unroll
    for (int o = 16; o; o >>= 1) v += __shfl_down_sync(0xffffffffu, v, o);
    if (lane == 0) sh8[wid] = v;
    __syncthreads();
    float r = (threadIdx.x < 8) ? sh8[threadIdx.x] : 0.0f;
    if (wid == 0) {
        #pragma unroll
        for (int o = 4; o; o >>= 1) r += __shfl_down_sync(0xffffffffu, r, o);
        if (lane == 0) sh8[0] = r;
    }
    __syncthreads();
    float res = sh8[0];
    __syncthreads();
    return res;
}

__global__ void ln_router_kernel(const float* __restrict__ x,
                                 const float* __restrict__ gamma,
                                 const float* __restrict__ beta,
                                 const float* __restrict__ Wr) {
    __shared__ float sh[8];
    __shared__ double shd[8][E_ROUTED];
    int t = blockIdx.x, d4 = threadIdx.x;
    int lane = threadIdx.x & 31, wid = threadIdx.x >> 5;
    float4 v = reinterpret_cast<const float4*>(x + (size_t)t * DMODEL)[d4];
    float mu = blockReduceSum256(v.x + v.y + v.z + v.w, sh) * (1.0f / DMODEL);
    float dx = v.x - mu, dy = v.y - mu, dz = v.z - mu, dw = v.w - mu;
    float var = blockReduceSum256(dx*dx + dy*dy + dz*dz + dw*dw, sh) * (1.0f / DMODEL);
    float inv = rsqrtf(var + 1e-5f);
    float4 gg = reinterpret_cast<const float4*>(gamma)[d4];
    float4 bb = reinterpret_cast<const float4*>(beta)[d4];
    float4 o;
    o.x = dx*inv*gg.x + bb.x; o.y = dy*inv*gg.y + bb.y;
    o.z = dz*inv*gg.z + bb.z; o.w = dw*inv*gg.w + bb.w;
    __half2* hrow = reinterpret_cast<__half2*>(g_ht + (size_t)t * DMODEL);
    hrow[d4*2+0] = __floats2half2_rn(o.x, o.y);
    hrow[d4*2+1] = __floats2half2_rn(o.z, o.w);

    const int d0 = d4 * 4;
    double acc[E_ROUTED];
    #pragma unroll
    for (int e = 0; e < E_ROUTED; e++) {
        acc[e] = (double)o.x * (double)Wr[(size_t)(d0+0)*E_ROUTED + e]
               + (double)o.y * (double)Wr[(size_t)(d0+1)*E_ROUTED + e]
               + (double)o.z * (double)Wr[(size_t)(d0+2)*E_ROUTED + e]
               + (double)o.w * (double)Wr[(size_t)(d0+3)*E_ROUTED + e];
    }
    #pragma unroll
    for (int e = 0; e < E_ROUTED; e++)
        #pragma unroll
        for (int off = 16; off; off >>= 1)
            acc[e] += __shfl_down_sync(0xffffffffu, acc[e], off);
    if (lane == 0)
        #pragma unroll
        for (int e = 0; e < E_ROUTED; e++) shd[wid][e] = acc[e];
    __syncthreads();
    if (threadIdx.x == 0) {
        float vv[E_ROUTED];
        #pragma unroll
        for (int e = 0; e < E_ROUTED; e++) {
            double s = 0.0;
            #pragma unroll
            for (int w = 0; w < 8; w++) s += shd[w][e];
            vv[e] = (float)s;
        }
        int i1 = 0;
        #pragma unroll
        for (int e = 1; e < E_ROUTED; e++) if (vv[e] > vv[i1]) i1 = e;
        int i2 = -1;
        #pragma unroll
        for (int e = 0; e < E_ROUTED; e++) {
            if (e == i1) continue;
            if (i2 < 0 || vv[e] > vv[i2]) i2 = e;
        }
        float m = vv[i1], e1 = expf(vv[i1]-m), e2 = expf(vv[i2]-m), invs = 1.0f/(e1+e2);
        g_topidx[t*2+0] = i1; g_topidx[t*2+1] = i2;
        g_gate[t*2+0] = e1*invs; g_gate[t*2+1] = e2*invs;
    }
}

// ---------------- 1) Transpose + fp16-convert ALL weights ----------------
__global__ void transpose_all(const float* __restrict__ W1, const float* __restrict__ W1s,
                              const float* __restrict__ W3, const float* __restrict__ W3s,
                              const float* __restrict__ W2, const float* __restrict__ W2s) {
    __shared__ float t[32][33];
    int z = blockIdx.z, which = z >> 3, e = z & 7;
    int R = (which < 2) ? DMODEL : DFF;
    int C = (which < 2) ? DFF : DMODEL;
    const float* rsrc = (which == 0) ? W1 : (which == 1) ? W3 : W2;
    const float* ssrc = (which == 0) ? W1s : (which == 1) ? W3s : W2s;
    const float* s = (e < E_ROUTED) ? rsrc + (size_t)e * WPER : ssrc;
    __half* d = ((which == 0) ? g_w1t : (which == 1) ? g_w3t : g_w2t) + (size_t)e * WPER;
    int rt = (which < 2) ? blockIdx.y : blockIdx.x;
    int ct = (which < 2) ? blockIdx.x : blockIdx.y;
    int tx = threadIdx.x, ty = threadIdx.y;
    #pragma unroll
    for (int i = 0; i < 32; i += 8)
        t[ty+i][tx] = s[(size_t)(rt*32 + ty + i) * C + ct*32 + tx];
    __syncthreads();
    #pragma unroll
    for (int i = 0; i < 32; i += 8)
        d[(size_t)(ct*32 + ty + i) * R + rt*32 + tx] = __float2half(t[tx][ty+i]);
}

// ---------------- 2) Dispatch positions ----------------
__global__ void pos_kernel() {
    int e = blockIdx.x;
    __shared__ int warpTot[8];
    int lane = threadIdx.x & 31, wid = threadIdx.x >> 5;
    int running = 0;
    for (int k = 0; k < TOPK; k++)
        for (int base = 0; base < T_TOK; base += 256) {
            int t = base + threadIdx.x;
            int match = (g_topidx[t*2+k] == e) ? 1 : 0;
            unsigned bal = __ballot_sync(0xffffffffu, match);
            int wpre = __popc(bal & ((1u << lane) - 1u));
            if (lane == 31) warpTot[wid] = wpre + match;
            __syncthreads();
            int wbase = 0;
            #pragma unroll
            for (int w = 0; w < 8; w++) if (w < wid) wbase += warpTot[w];
            if (match) {
                int p = running + wbase + wpre;
                if (p < CAPACITY) { g_pos[k*T_TOK+t] = p; g_slot_token[e*CAPACITY+p] = t; }
                else g_pos[k*T_TOK+t] = -1;
            }
            int tot = 0;
            #pragma unroll
            for (int w = 0; w < 8; w++) tot += warpTot[w];
            running += tot;
            __syncthreads();
        }
    if (threadIdx.x == 0) g_count[e] = (running < CAPACITY) ? running : CAPACITY;
}

// ================= 3) Fused W1+W3 fp16 mma GEMM + SwiGLU =================
// CTA 64M x 64N per matrix; 8 warps = {W1,W3} x 2m x 2n; warp 32x32 (32 accs).
// 4-stage ring (R9-proven wait ledger), 3 CTAs/SM. c3 shipped via smem once/CTA.
#define LDH 40
#define G13_AOFF  0
#define G13_B1OFF 5120
#define G13_B3OFF 10240
#define G13_STGB  15360
#define G13_SMEM  (4 * G13_STGB)         // 61440 B

__global__ void __launch_bounds__(256, 3) gemm13_mma() {
    extern __shared__ char smB[];
    const int e = blockIdx.z;
    const int n0 = blockIdx.x * 64;
    const int m0 = blockIdx.y * 64;
    const int cnt = (e < E_ROUTED) ? g_count[e] : T_TOK;
    if (m0 >= cnt) return;
    const int tid = threadIdx.x, wid = tid >> 5, lane = tid & 31;
    const int mat = wid >> 2, wm = (wid >> 1) & 1, wn = wid & 1;
    const int gid = lane >> 2, t4 = lane & 3;

    const __half* w1e = g_w1t + (size_t)e * WPER;
    const __half* w3e = g_w3t + (size_t)e * WPER;

    // loaders: 1 A + 1 B1 + 1 B3 cp16 per thread (r in 0..63, c in 0..3)
    const int r = tid >> 2, c = tid & 3;
    int mg = m0 + r;
    int tok = (e < E_ROUTED) ? ((mg < cnt) ? g_slot_token[e*CAPACITY + mg] : 0) : mg;
    const __half* agh  = g_ht + (size_t)tok * DMODEL + c*8;
    const __half* b1gh = w1e + (size_t)(n0 + r) * DMODEL + c*8;
    const __half* b3gh = w3e + (size_t)(n0 + r) * DMODEL + c*8;
    const uint32_t loff = (uint32_t)(r*80 + c*16);
    const uint32_t sbase = smem_u32(smB);

    const uint32_t lhalf = (uint32_t)(lane & 15);
    const uint32_t khalf = (uint32_t)(lane >> 4) * 16u;
    uint32_t aAddr[2], bAddr[2];
    #pragma unroll
    for (int t = 0; t < 2; t++)
        aAddr[t] = (uint32_t)((wm*32 + t*16) + lhalf) * 80u + khalf;
    #pragma unroll
    for (int p = 0; p < 2; p++)
        bAddr[p] = (uint32_t)((wn*32 + p*16) + lhalf) * 80u + khalf;
    const uint32_t bmoff = (mat == 0) ? G13_B1OFF : G13_B3OFF;

    float cc[2][4][4] = {};

    auto load_stage = [&](int s, int j) {
        uint32_t st = sbase + (uint32_t)s * G13_STGB;
        cp16(st + G13_AOFF  + loff, agh  + j*32);
        cp16(st + G13_B1OFF + loff, b1gh + j*32);
        cp16(st + G13_B3OFF + loff, b3gh + j*32);
        cp_commit();
    };
    auto compute = [&](int s) {
        const uint32_t stA = sbase + (uint32_t)s * G13_STGB;
        const uint32_t stB = stA + bmoff;
        #pragma unroll
        for (int ks = 0; ks < 2; ks++) {
            const uint32_t ko = (uint32_t)ks * 32u;
            uint32_t a[2][4];
            ldsm_x4(a[0][0], a[0][1], a[0][2], a[0][3], stA + aAddr[0] + ko);
            ldsm_x4(a[1][0], a[1][1], a[1][2], a[1][3], stA + aAddr[1] + ko);
            #pragma unroll
            for (int p = 0; p < 2; p++) {
                uint32_t b0a, b0b, b1a, b1b;
                ldsm_x4(b0a, b0b, b1a, b1b, stB + bAddr[p] + ko);
                #pragma unroll
                for (int t = 0; t < 2; t++) {
                    mma_f16(cc[t][2*p],   a[t][0], a[t][1], a[t][2], a[t][3], b0a, b1a);
                    mma_f16(cc[t][2*p+1], a[t][0], a[t][1], a[t][2], a[t][3], b0b, b1b);
                }
            }
        }
    };

    const int nch = DMODEL/32;   // 32
    load_stage(0, 0); load_stage(1, 1); load_stage(2, 2);
    int s = 0;
    #pragma unroll 1
    for (int j = 0; j < nch; ++j) {
        if (j < nch - 2)      cp_wait<2>();
        else if (j == nch-2)  cp_wait<1>();
        else                  cp_wait<0>();
        __syncthreads();
        compute(s);
        if (j + 3 < nch) load_stage((s + 3) & 3, j + 3);
        s = (s + 1) & 3;
    }

    // ---- cross-warp exchange of c3, then SwiGLU store by W1-warps ----
    __syncthreads();                      // all reads of ring done
    float* ex = reinterpret_cast<float*>(smB);
    const int slot = ((wm*2 + wn)*32 + lane) * 32;
    if (mat == 1) {
        #pragma unroll
        for (int t = 0; t < 2; t++)
            #pragma unroll
            for (int u = 0; u < 4; u++)
                #pragma unroll
                for (int ci = 0; ci < 4; ci++)
                    ex[slot + t*16 + u*4 + ci] = cc[t][u][ci];
    }
    __syncthreads();
    if (mat == 0) {
        __half* dstb = (e < E_ROUTED) ? g_ub + (size_t)e * CAPACITY * DFF : g_ubs;
        #pragma unroll
        for (int t = 0; t < 2; t++)
            #pragma unroll
            for (int half = 0; half < 2; half++) {
                int rr = m0 + wm*32 + t*16 + gid + half*8;
                if (rr < cnt) {
                    __half* drow = dstb + (size_t)rr * DFF + n0 + wn*32 + t4*2;
                    #pragma unroll
                    for (int u = 0; u < 4; u++) {
                        int ci = half*2;
                        float b0 = ex[slot + t*16 + u*4 + ci];
                        float b1 = ex[slot + t*16 + u*4 + ci + 1];
                        float ux = silu_f(cc[t][u][ci])   * b0;
                        float uy = silu_f(cc[t][u][ci+1]) * b1;
                        *reinterpret_cast<__half2*>(drow + u*8) = __floats2half2_rn(ux, uy);
                    }
                }
            }
    }
}

// ================= 4) W2 fp16 mma GEMM =================
// CTA 64M x 128N; 8 warps = 2m x 4n; warp 32x32 (32 accs). 4-stage, 3 CTAs/SM.
#define G2_AOFF  0
#define G2_BOFF  5120
#define G2_STGB  15360                   // A 5120 + B 10240
#define G2_SMEM  (4 * G2_STGB)           // 61440 B

__global__ void __launch_bounds__(256, 3) gemm2_mma() {
    extern __shared__ char smB[];
    const int e = blockIdx.z;
    const int n0 = blockIdx.x * 128;
    const int m0 = blockIdx.y * 64;
    const int cnt = (e < E_ROUTED) ? g_count[e] : T_TOK;
    if (m0 >= cnt) return;
    const int tid = threadIdx.x, wid = tid >> 5, lane = tid & 31;
    const int wm = wid >> 2, wn = wid & 3;
    const int gid = lane >> 2, t4 = lane & 3;

    const __half* Abase = (e < E_ROUTED) ? g_ub + (size_t)e * CAPACITY * DFF : g_ubs;
    const __half* w2e = g_w2t + (size_t)e * WPER;

    // A loader: 1/thread (r 0..63), B loader: 2/thread (n 0..127)
    const int r = tid >> 2, c = tid & 3;
    int mg = m0 + r;
    const __half* agh = Abase + (size_t)((mg < cnt) ? mg : 0) * DFF + c*8;
    const uint32_t aoffB = (uint32_t)(r*80 + c*16);
    const __half* bgh[2]; uint32_t boffB[2];
    #pragma unroll
    for (int i = 0; i < 2; i++) {
        int idx = tid + i*256;
        int n = idx >> 2, cc2 = idx & 3;
        bgh[i] = w2e + (size_t)(n0 + n) * DFF + cc2*8;
        boffB[i] = (uint32_t)(n*80 + cc2*16);
    }
    const uint32_t sbase = smem_u32(smB);

    const uint32_t lhalf = (uint32_t)(lane & 15);
    const uint32_t khalf = (uint32_t)(lane >> 4) * 16u;
    uint32_t aAddr[2], bAddr[2];
    #pragma unroll
    for (int t = 0; t < 2; t++)
        aAddr[t] = (uint32_t)((wm*32 + t*16) + lhalf) * 80u + khalf;
    #pragma unroll
    for (int p = 0; p < 2; p++)
        bAddr[p] = (uint32_t)((wn*32 + p*16) + lhalf) * 80u + khalf;

    float cc[2][4][4] = {};

    auto load_stage = [&](int s, int j) {
        uint32_t st = sbase + (uint32_t)s * G2_STGB;
        cp16(st + G2_AOFF + aoffB, agh + j*32);
        size_t roff = (size_t)j * 32;
        cp16(st + G2_BOFF + boffB[0], bgh[0] + roff);
        cp16(st + G2_BOFF + boffB[1], bgh[1] + roff);
        cp_commit();
    };
    auto compute = [&](int s) {
        const uint32_t stA = sbase + (uint32_t)s * G2_STGB;
        const uint32_t stB = stA + G2_BOFF;
        #pragma unroll
        for (int ks = 0; ks < 2; ks++) {
            const uint32_t ko = (uint32_t)ks * 32u;
            uint32_t a[2][4];
            ldsm_x4(a[0][0], a[0][1], a[0][2], a[0][3], stA + aAddr[0] + ko);
            ldsm_x4(a[1][0], a[1][1], a[1][2], a[1][3], stA + aAddr[1] + ko);
            #pragma unroll
            for (int p = 0; p < 2; p++) {
                uint32_t b0a, b0b, b1a, b1b;
                ldsm_x4(b0a, b0b, b1a, b1b, stB + bAddr[p] + ko);
                #pragma unroll
                for (int t = 0; t < 2; t++) {
                    mma_f16(cc[t][2*p],   a[t][0], a[t][1], a[t][2], a[t][3], b0a, b1a);
                    mma_f16(cc[t][2*p+1], a[t][0], a[t][1], a[t][2], a[t][3], b0b, b1b);
                }
            }
        }
    };

    const int nch = DFF/32;   // 128
    load_stage(0, 0); load_stage(1, 1); load_stage(2, 2);
    int s = 0;
    #pragma unroll 1
    for (int j = 0; j < nch; ++j) {
        if (j < nch - 2)      cp_wait<2>();
        else if (j == nch-2)  cp_wait<1>();
        else                  cp_wait<0>();
        __syncthreads();
        compute(s);
        if (j + 3 < nch) load_stage((s + 3) & 3, j + 3);
        s = (s + 1) & 3;
    }

    float* dstb = (e < E_ROUTED) ? g_ye + (size_t)e * CAPACITY * DMODEL : g_ys;
    #pragma unroll
    for (int t = 0; t < 2; t++)
        #pragma unroll
        for (int half = 0; half < 2; half++) {
            int rr = m0 + wm*32 + t*16 + gid + half*8;
            if (rr < cnt) {
                float* drow = dstb + (size_t)rr * DMODEL + n0 + wn*32 + t4*2;
                #pragma unroll
                for (int u = 0; u < 4; u++) {
                    int ci = half*2;
                    float2 o; o.x = cc[t][u][ci]; o.y = cc[t][u][ci+1];
                    *reinterpret_cast<float2*>(drow + u*8) = o;
                }
            }
        }
}

// ---------------- 5) Combine ----------------
__global__ void combine_kernel(float* __restrict__ out) {
    int t = blockIdx.x, d4 = threadIdx.x;
    float4 o = reinterpret_cast<const float4*>(g_ys + (size_t)t * DMODEL)[d4];
    #pragma unroll
    for (int k = 0; k < TOPK; k++) {
        int p = g_pos[k * T_TOK + t];
        if (p >= 0) {
            int e = g_topidx[t*2+k];
            float gv = g_gate[t*2+k];
            float4 y = reinterpret_cast<const float4*>(g_ye + ((size_t)e*CAPACITY + p) * DMODEL)[d4];
            o.x += gv*y.x; o.y += gv*y.y; o.z += gv*y.z; o.w += gv*y.w;
        }
    }
    reinterpret_cast<float4*>(out + (size_t)t * DMODEL)[d4] = o;
}

// ---------------- launch ----------------
extern "C" void kernel_launch(void* const* d_in, const int* in_sizes, int n_in,
                              void* d_out, int out_size) {
    (void)in_sizes; (void)n_in; (void)out_size;
    const float* x    = (const float*)d_in[0];
    const float* ln_g = (const float*)d_in[1];
    const float* ln_b = (const float*)d_in[2];
    const float* Wr   = (const float*)d_in[3];
    const float* W1   = (const float*)d_in[4];
    const float* W3   = (const float*)d_in[5];
    const float* W2   = (const float*)d_in[6];
    const float* W1s  = (const float*)d_in[7];
    const float* W3s  = (const float*)d_in[8];
    const float* W2s  = (const float*)d_in[9];
    float* out = (float*)d_out;

    cudaFuncSetAttribute(gemm13_mma, cudaFuncAttributeMaxDynamicSharedMemorySize, G13_SMEM);
    cudaFuncSetAttribute(gemm2_mma,  cudaFuncAttributeMaxDynamicSharedMemorySize, G2_SMEM);

    ln_router_kernel<<<T_TOK, 256>>>(x, ln_g, ln_b, Wr);                          // 0
    transpose_all<<<dim3(128, 32, 24), dim3(32, 8)>>>(W1, W1s, W3, W3s, W2, W2s); // 1
    pos_kernel<<<E_ROUTED, 256>>>();                                              // 2
    gemm13_mma<<<dim3(DFF/64, T_TOK/64, E_ROUTED + 1), 256, G13_SMEM>>>();        // 3 <- ncu slot
    gemm2_mma <<<dim3(DMODEL/128, T_TOK/64, E_ROUTED + 1), 256, G2_SMEM>>>();     // 4
    combine_kernel<<<T_TOK, 256>>>(out);                                          // 5
}

// round 14
// speedup vs baseline: 1.0848x; 1.0848x over previous
#include <cuda_runtime.h>
#include <cuda_fp16.h>
#include <math.h>
#include <stdint.h>

#define T_TOK     8192
#define DMODEL    1024
#define DFF       4096
#define E_ROUTED  7
#define TOPK      2
#define CAPACITY  2926
#define WPER      ((size_t)DMODEL * DFF)

// ---------------- scratch ----------------
__device__ __half g_ht[(size_t)T_TOK * DMODEL];
__device__ int    g_topidx[T_TOK * TOPK];
__device__ float  g_gate[T_TOK * TOPK];
__device__ int    g_pos[TOPK * T_TOK];
__device__ int    g_slot_token[E_ROUTED * CAPACITY];
__device__ int    g_count[E_ROUTED];
__device__ __half g_w1t[8 * WPER];                       // [e][F][D] K-major fp16
__device__ __half g_w3t[8 * WPER];
__device__ __half g_w2t[8 * WPER];                       // [e][D][F] K-major fp16
__device__ __half g_ub [(size_t)E_ROUTED * CAPACITY * DFF];
__device__ __half g_ubs[(size_t)T_TOK * DFF];
__device__ float  g_ye [(size_t)E_ROUTED * CAPACITY * DMODEL];
__device__ float  g_ys [(size_t)T_TOK * DMODEL];

// ---------------- helpers ----------------
__device__ __forceinline__ uint32_t smem_u32(const void* p) {
    return (uint32_t)__cvta_generic_to_shared(p);
}
__device__ __forceinline__ void cp16(uint32_t d, const void* s) {
    asm volatile("cp.async.cg.shared.global [%0], [%1], 16;" :: "r"(d), "l"(s) : "memory");
}
__device__ __forceinline__ void cp_commit() {
    asm volatile("cp.async.commit_group;" ::: "memory");
}
template <int N>
__device__ __forceinline__ void cp_wait() {
    asm volatile("cp.async.wait_group %0;" :: "n"(N) : "memory");
}
__device__ __forceinline__ void mma_f16(float c[4], uint32_t a0, uint32_t a1,
                                        uint32_t a2, uint32_t a3,
                                        uint32_t b0, uint32_t b1) {
    asm volatile(
        "mma.sync.aligned.m16n8k16.row.col.f32.f16.f16.f32 "
        "{%0,%1,%2,%3},{%4,%5,%6,%7},{%8,%9},{%0,%1,%2,%3};"
        : "+f"(c[0]), "+f"(c[1]), "+f"(c[2]), "+f"(c[3])
        : "r"(a0), "r"(a1), "r"(a2), "r"(a3), "r"(b0), "r"(b1));
}
__device__ __forceinline__ float silu_f(float v) { return v / (1.0f + __expf(-v)); }

// ---------------- 0) Fused LayerNorm + Router ----------------
__device__ __forceinline__ float blockReduceSum256(float v, float* sh8) {
    int lane = threadIdx.x & 31, wid = threadIdx.x >> 5;
    #pragma unroll
    for (int o = 16; o; o >>= 1) v += __shfl_down_sync(0xffffffffu, v, o);
    if (lane == 0) sh8[wid] = v;
    __syncthreads();
    float r = (threadIdx.x < 8) ? sh8[threadIdx.x] : 0.0f;
    if (wid == 0) {
        #pragma unroll
        for (int o = 4; o; o >>= 1) r += __shfl_down_sync(0xffffffffu, r, o);
        if (lane == 0) sh8[0] = r;
    }
    __syncthreads();
    float res = sh8[0];
    __syncthreads();
    return res;
}

__global__ void ln_router_kernel(const float* __restrict__ x,
                                 const float* __restrict__ gamma,
                                 const float* __restrict__ beta,
                                 const float* __restrict__ Wr) {
    __shared__ float sh[8];
    __shared__ double shd[8][E_ROUTED];
    int t = blockIdx.x, d4 = threadIdx.x;
    int lane = threadIdx.x & 31, wid = threadIdx.x >> 5;
    float4 v = reinterpret_cast<const float4*>(x + (size_t)t * DMODEL)[d4];
    float mu = blockReduceSum256(v.x + v.y + v.z + v.w, sh) * (1.0f / DMODEL);
    float dx = v.x - mu, dy = v.y - mu, dz = v.z - mu, dw = v.w - mu;
    float var = blockReduceSum256(dx*dx + dy*dy + dz*dz + dw*dw, sh) * (1.0f / DMODEL);
    float inv = rsqrtf(var + 1e-5f);
    float4 gg = reinterpret_cast<const float4*>(gamma)[d4];
    float4 bb = reinterpret_cast<const float4*>(beta)[d4];
    float4 o;
    o.x = dx*inv*gg.x + bb.x; o.y = dy*inv*gg.y + bb.y;
    o.z = dz*inv*gg.z + bb.z; o.w = dw*inv*gg.w + bb.w;
    __half2* hrow = reinterpret_cast<__half2*>(g_ht + (size_t)t * DMODEL);
    hrow[d4*2+0] = __floats2half2_rn(o.x, o.y);
    hrow[d4*2+1] = __floats2half2_rn(o.z, o.w);

    const int d0 = d4 * 4;
    double acc[E_ROUTED];
    #pragma unroll
    for (int e = 0; e < E_ROUTED; e++) {
        acc[e] = (double)o.x * (double)Wr[(size_t)(d0+0)*E_ROUTED + e]
               + (double)o.y * (double)Wr[(size_t)(d0+1)*E_ROUTED + e]
               + (double)o.z * (double)Wr[(size_t)(d0+2)*E_ROUTED + e]
               + (double)o.w * (double)Wr[(size_t)(d0+3)*E_ROUTED + e];
    }
    #pragma unroll
    for (int e = 0; e < E_ROUTED; e++)
        #pragma unroll
        for (int off = 16; off; off >>= 1)
            acc[e] += __shfl_down_sync(0xffffffffu, acc[e], off);
    if (lane == 0)
        #pragma unroll
        for (int e = 0; e < E_ROUTED; e++) shd[wid][e] = acc[e];
    __syncthreads();
    if (threadIdx.x == 0) {
        float vv[E_ROUTED];
        #pragma unroll
        for (int e = 0; e < E_ROUTED; e++) {
            double s = 0.0;
            #pragma unroll
            for (int w = 0; w < 8; w++) s += shd[w][e];
            vv[e] = (float)s;
        }
        int i1 = 0;
        #pragma unroll
        for (int e = 1; e < E_ROUTED; e++) if (vv[e] > vv[i1]) i1 = e;
        int i2 = -1;
        #pragma unroll
        for (int e = 0; e < E_ROUTED; e++) {
            if (e == i1) continue;
            if (i2 < 0 || vv[e] > vv[i2]) i2 = e;
        }
        float m = vv[i1], e1 = expf(vv[i1]-m), e2 = expf(vv[i2]-m), invs = 1.0f/(e1+e2);
        g_topidx[t*2+0] = i1; g_topidx[t*2+1] = i2;
        g_gate[t*2+0] = e1*invs; g_gate[t*2+1] = e2*invs;
    }
}

// ---------------- 1) Transpose + fp16-convert, 64x64 tiles ----------------
// which = z>>3: 0->W1, 1->W3, 2->W2; e = z&7 (7 -> shared).
// Reads 64 fp32 rows of 64 cols (256B), writes 64 fp16 rows of 64 (128B).
__global__ void transpose_all(const float* __restrict__ W1, const float* __restrict__ W1s,
                              const float* __restrict__ W3, const float* __restrict__ W3s,
                              const float* __restrict__ W2, const float* __restrict__ W2s) {
    __shared__ float t[64][65];
    int z = blockIdx.z, which = z >> 3, e = z & 7;
    int R = (which < 2) ? DMODEL : DFF;
    int C = (which < 2) ? DFF : DMODEL;
    const float* rsrc = (which == 0) ? W1 : (which == 1) ? W3 : W2;
    const float* ssrc = (which == 0) ? W1s : (which == 1) ? W3s : W2s;
    const float* s = (e < E_ROUTED) ? rsrc + (size_t)e * WPER : ssrc;
    __half* d = ((which == 0) ? g_w1t : (which == 1) ? g_w3t : g_w2t) + (size_t)e * WPER;
    int rt = (which < 2) ? blockIdx.y : blockIdx.x;   // R/64 tiles
    int ct = (which < 2) ? blockIdx.x : blockIdx.y;   // C/64 tiles
    int tx = threadIdx.x & 63, ty = threadIdx.x >> 6;  // 256 thr: 64 x 4
    #pragma unroll
    for (int i = 0; i < 64; i += 4)
        t[ty + i][tx] = s[(size_t)(rt*64 + ty + i) * C + ct*64 + tx];
    __syncthreads();
    #pragma unroll
    for (int i = 0; i < 64; i += 4)
        d[(size_t)(ct*64 + ty + i) * R + rt*64 + tx] = __float2half(t[tx][ty + i]);
}

// ---------------- 2) Dispatch positions ----------------
__global__ void pos_kernel() {
    int e = blockIdx.x;
    __shared__ int warpTot[8];
    int lane = threadIdx.x & 31, wid = threadIdx.x >> 5;
    int running = 0;
    for (int k = 0; k < TOPK; k++)
        for (int base = 0; base < T_TOK; base += 256) {
            int t = base + threadIdx.x;
            int match = (g_topidx[t*2+k] == e) ? 1 : 0;
            unsigned bal = __ballot_sync(0xffffffffu, match);
            int wpre = __popc(bal & ((1u << lane) - 1u));
            if (lane == 31) warpTot[wid] = wpre + match;
            __syncthreads();
            int wbase = 0;
            #pragma unroll
            for (int w = 0; w < 8; w++) if (w < wid) wbase += warpTot[w];
            if (match) {
                int p = running + wbase + wpre;
                if (p < CAPACITY) { g_pos[k*T_TOK+t] = p; g_slot_token[e*CAPACITY+p] = t; }
                else g_pos[k*T_TOK+t] = -1;
            }
            int tot = 0;
            #pragma unroll
            for (int w = 0; w < 8; w++) tot += warpTot[w];
            running += tot;
            __syncthreads();
        }
    if (threadIdx.x == 0) g_count[e] = (running < CAPACITY) ? running : CAPACITY;
}

// ================= 3) Fused W1+W3 fp16 mma GEMM + SwiGLU (R10 config) ======
// BM=128, BN=64 each, BK=32. 5-stage ring, 1 barrier / 2 chunks, loads first.
#define LDH 40                           // halfs per row (80 B)
#define G13_A_B   (128*LDH*2)            // 10240 B
#define G13_B1_O  G13_A_B
#define G13_B3_O  (G13_A_B + 64*LDH*2)
#define G13_STGB  (G13_A_B + 2*64*LDH*2) // 20480 B
#define G13_SMEM  (5 * G13_STGB)         // 102400 B

__global__ void __launch_bounds__(256, 2) gemm13_mma() {
    extern __shared__ char smB[];
    const int e = blockIdx.z;
    const int n0 = blockIdx.x * 64;
    const int m0 = blockIdx.y * 128;
    const int cnt = (e < E_ROUTED) ? g_count[e] : T_TOK;
    if (m0 >= cnt) return;
    const int tid = threadIdx.x, wid = tid >> 5, lane = tid & 31;
    const int wm = wid >> 1, wn = wid & 1;
    const int gid = lane >> 2, t4 = lane & 3;

    const __half* w1e = g_w1t + (size_t)e * WPER;
    const __half* w3e = g_w3t + (size_t)e * WPER;

    const __half* agh[2]; uint32_t aoffB[2];
    #pragma unroll
    for (int i = 0; i < 2; i++) {
        int idx = tid + i*256;
        int r = idx >> 2, c = idx & 3;
        int mg = m0 + r;
        int tok = (e < E_ROUTED) ? ((mg < cnt) ? g_slot_token[e*CAPACITY + mg] : 0) : mg;
        agh[i] = g_ht + (size_t)tok * DMODEL + c*8;
        aoffB[i] = (uint32_t)(r*80 + c*16);
    }
    const __half* b1gh; const __half* b3gh; uint32_t boffB;
    {
        int n = tid >> 2, c = tid & 3;
        b1gh = w1e + (size_t)(n0 + n) * DMODEL + c*8;
        b3gh = w3e + (size_t)(n0 + n) * DMODEL + c*8;
        boffB = (uint32_t)(n*80 + c*16);
    }
    const uint32_t sbase = smem_u32(smB);

    float c1[2][4][4] = {};
    float c3[2][4][4] = {};

    auto load_stage = [&](int s, int j) {
        uint32_t st = sbase + (uint32_t)s * G13_STGB;
        cp16(st + aoffB[0], agh[0] + j*32);
        cp16(st + aoffB[1], agh[1] + j*32);
        cp16(st + G13_B1_O + boffB, b1gh + j*32);
        cp16(st + G13_B3_O + boffB, b3gh + j*32);
        cp_commit();
    };
    auto compute = [&](int s) {
        const float* dummy = nullptr; (void)dummy;
        const char* stage = smB + s * G13_STGB;
        const uint32_t* A  = (const uint32_t*)(stage) + (wm*32)*20;
        const uint32_t* B1 = (const uint32_t*)(stage + G13_B1_O) + (wn*32)*20;
        const uint32_t* B3 = (const uint32_t*)(stage + G13_B3_O) + (wn*32)*20;
        #pragma unroll
        for (int ks = 0; ks < 2; ks++) {
            const int kb = ks*8 + t4;
            uint32_t a[2][4];
            #pragma unroll
            for (int t = 0; t < 2; t++) {
                int r = t*16 + gid;
                a[t][0] = A[r*20 + kb];
                a[t][1] = A[(r+8)*20 + kb];
                a[t][2] = A[r*20 + kb + 4];
                a[t][3] = A[(r+8)*20 + kb + 4];
            }
            #pragma unroll
            for (int u = 0; u < 4; u++) {
                const int nr = (u*8 + gid)*20;
                uint32_t p0 = B1[nr + kb], p1 = B1[nr + kb + 4];
                uint32_t q0 = B3[nr + kb], q1 = B3[nr + kb + 4];
                #pragma unroll
                for (int t = 0; t < 2; t++) {
                    mma_f16(c1[t][2*(u>>1)+(u&1)], a[t][0], a[t][1], a[t][2], a[t][3], p0, p1);
                    mma_f16(c3[t][2*(u>>1)+(u&1)], a[t][0], a[t][1], a[t][2], a[t][3], q0, q1);
                }
            }
        }
    };

    const int nch = DMODEL/32;   // 32 (even)
    load_stage(0, 0); load_stage(1, 1); load_stage(2, 2);
    int s = 0;
    #pragma unroll 1
    for (int j = 0; j < nch; j += 2) {
        if (j < nch - 2) cp_wait<1>();
        else             cp_wait<0>();   // TAIL pair
        __syncthreads();
        // prefetch first (targets stages retired before this barrier)
        if (j + 3 < nch) { int s3 = s + 3; if (s3 >= 5) s3 -= 5; load_stage(s3, j + 3); }
        if (j + 4 < nch) { int s4 = s + 4; if (s4 >= 5) s4 -= 5; load_stage(s4, j + 4); }
        int s1 = s + 1; if (s1 >= 5) s1 -= 5;
        compute(s);
        compute(s1);
        s += 2; if (s >= 5) s -= 5;
    }

    __half* dstb = (e < E_ROUTED) ? g_ub + (size_t)e * CAPACITY * DFF : g_ubs;
    #pragma unroll
    for (int t = 0; t < 2; t++)
        #pragma unroll
        for (int half = 0; half < 2; half++) {
            int r = m0 + wm*32 + t*16 + gid + half*8;
            if (r < cnt) {
                __half* drow = dstb + (size_t)r * DFF + n0 + wn*32 + t4*2;
                #pragma unroll
                for (int u = 0; u < 4; u++) {
                    int ci = half*2;
                    float ux = silu_f(c1[t][u][ci])   * c3[t][u][ci];
                    float uy = silu_f(c1[t][u][ci+1]) * c3[t][u][ci+1];
                    *reinterpret_cast<__half2*>(drow + u*8) = __floats2half2_rn(ux, uy);
                }
            }
        }
}

// ================= 4) W2 fp16 mma GEMM (R10 config) =================
#define G2_A_B  (128*LDH*2)              // 10240 B
#define G2_B_O  G2_A_B
#define G2_STGB (2 * G2_A_B)             // 20480 B
#define G2_SMEM (5 * G2_STGB)            // 102400 B

__global__ void __launch_bounds__(256, 2) gemm2_mma() {
    extern __shared__ char smB[];
    const int e = blockIdx.z;
    const int n0 = blockIdx.x * 128;
    const int m0 = blockIdx.y * 128;
    const int cnt = (e < E_ROUTED) ? g_count[e] : T_TOK;
    if (m0 >= cnt) return;
    const int tid = threadIdx.x, wid = tid >> 5, lane = tid & 31;
    const int wm = wid >> 1, wn = wid & 1;
    const int gid = lane >> 2, t4 = lane & 3;

    const __half* Abase = (e < E_ROUTED) ? g_ub + (size_t)e * CAPACITY * DFF : g_ubs;
    const __half* w2e = g_w2t + (size_t)e * WPER;

    const __half* agh[2]; uint32_t aoffB[2];
    #pragma unroll
    for (int i = 0; i < 2; i++) {
        int idx = tid + i*256;
        int r = idx >> 2, c = idx & 3;
        int mg = m0 + r;
        agh[i] = Abase + (size_t)((mg < cnt) ? mg : 0) * DFF + c*8;
        aoffB[i] = (uint32_t)(r*80 + c*16);
    }
    const __half* bgh[2]; uint32_t boffB[2];
    #pragma unroll
    for (int i = 0; i < 2; i++) {
        int idx = tid + i*256;
        int n = idx >> 2, c = idx & 3;
        bgh[i] = w2e + (size_t)(n0 + n) * DFF + c*8;
        boffB[i] = (uint32_t)(n*80 + c*16);
    }
    const uint32_t sbase = smem_u32(smB);

    float cc[2][8][4] = {};

    auto load_stage = [&](int s, int j) {
        uint32_t st = sbase + (uint32_t)s * G2_STGB;
        cp16(st + aoffB[0], agh[0] + j*32);
        cp16(st + aoffB[1], agh[1] + j*32);
        cp16(st + G2_B_O + boffB[0], bgh[0] + j*32);
        cp16(st + G2_B_O + boffB[1], bgh[1] + j*32);
        cp_commit();
    };
    auto compute = [&](int s) {
        const char* stage = smB + s * G2_STGB;
        const uint32_t* A = (const uint32_t*)(stage) + (wm*32)*20;
        const uint32_t* B = (const uint32_t*)(stage + G2_B_O) + (wn*64)*20;
        #pragma unroll
        for (int ks = 0; ks < 2; ks++) {
            const int kb = ks*8 + t4;
            uint32_t a[2][4];
            #pragma unroll
            for (int t = 0; t < 2; t++) {
                int r = t*16 + gid;
                a[t][0] = A[r*20 + kb];
                a[t][1] = A[(r+8)*20 + kb];
                a[t][2] = A[r*20 + kb + 4];
                a[t][3] = A[(r+8)*20 + kb + 4];
            }
            #pragma unroll
            for (int u = 0; u < 8; u++) {
                const int nr = (u*8 + gid)*20;
                uint32_t b0 = B[nr + kb], b1 = B[nr + kb + 4];
                #pragma unroll
                for (int t = 0; t < 2; t++)
                    mma_f16(cc[t][u], a[t][0], a[t][1], a[t][2], a[t][3], b0, b1);
            }
        }
    };

    const int nch = DFF/32;   // 128 (even)
    load_stage(0, 0); load_stage(1, 1); load_stage(2, 2);
    int s = 0;
    #pragma unroll 1
    for (int j = 0; j < nch; j += 2) {
        if (j < nch - 2) cp_wait<1>();
        else             cp_wait<0>();   // TAIL pair
        __syncthreads();
        if (j + 3 < nch) { int s3 = s + 3; if (s3 >= 5) s3 -= 5; load_stage(s3, j + 3); }
        if (j + 4 < nch) { int s4 = s + 4; if (s4 >= 5) s4 -= 5; load_stage(s4, j + 4); }
        int s1 = s + 1; if (s1 >= 5) s1 -= 5;
        compute(s);
        compute(s1);
        s += 2; if (s >= 5) s -= 5;
    }

    float* dstb = (e < E_ROUTED) ? g_ye + (size_t)e * CAPACITY * DMODEL : g_ys;
    #pragma unroll
    for (int t = 0; t < 2; t++)
        #pragma unroll
        for (int half = 0; half < 2; half++) {
            int r = m0 + wm*32 + t*16 + gid + half*8;
            if (r < cnt) {
                float* drow = dstb + (size_t)r * DMODEL + n0 + wn*64 + t4*2;
                #pragma unroll
                for (int u = 0; u < 8; u++) {
                    int ci = half*2;
                    float2 o; o.x = cc[t][u][ci]; o.y = cc[t][u][ci+1];
                    *reinterpret_cast<float2*>(drow + u*8) = o;
                }
            }
        }
}

// ---------------- 5) Combine ----------------
__global__ void combine_kernel(float* __restrict__ out) {
    int t = blockIdx.x, d4 = threadIdx.x;
    float4 o = reinterpret_cast<const float4*>(g_ys + (size_t)t * DMODEL)[d4];
    #pragma unroll
    for (int k = 0; k < TOPK; k++) {
        int p = g_pos[k * T_TOK + t];
        if (p >= 0) {
            int e = g_topidx[t*2+k];
            float gv = g_gate[t*2+k];
            float4 y = reinterpret_cast<const float4*>(g_ye + ((size_t)e*CAPACITY + p) * DMODEL)[d4];
            o.x += gv*y.x; o.y += gv*y.y; o.z += gv*y.z; o.w += gv*y.w;
        }
    }
    reinterpret_cast<float4*>(out + (size_t)t * DMODEL)[d4] = o;
}

// ---------------- launch ----------------
extern "C" void kernel_launch(void* const* d_in, const int* in_sizes, int n_in,
                              void* d_out, int out_size) {
    (void)in_sizes; (void)n_in; (void)out_size;
    const float* x    = (const float*)d_in[0];
    const float* ln_g = (const float*)d_in[1];
    const float* ln_b = (const float*)d_in[2];
    const float* Wr   = (const float*)d_in[3];
    const float* W1   = (const float*)d_in[4];
    const float* W3   = (const float*)d_in[5];
    const float* W2   = (const float*)d_in[6];
    const float* W1s  = (const float*)d_in[7];
    const float* W3s  = (const float*)d_in[8];
    const float* W2s  = (const float*)d_in[9];
    float* out = (float*)d_out;

    cudaFuncSetAttribute(gemm13_mma, cudaFuncAttributeMaxDynamicSharedMemorySize, G13_SMEM);
    cudaFuncSetAttribute(gemm2_mma,  cudaFuncAttributeMaxDynamicSharedMemorySize, G2_SMEM);

    ln_router_kernel<<<T_TOK, 256>>>(x, ln_g, ln_b, Wr);                          // 0
    transpose_all<<<dim3(64, 16, 24), 256>>>(W1, W1s, W3, W3s, W2, W2s);          // 1
    pos_kernel<<<E_ROUTED, 256>>>();                                              // 2
    gemm13_mma<<<dim3(DFF/64, T_TOK/128, E_ROUTED + 1), 256, G13_SMEM>>>();       // 3 <- ncu slot
    gemm2_mma <<<dim3(DMODEL/128, T_TOK/128, E_ROUTED + 1), 256, G2_SMEM>>>();    // 4
    combine_kernel<<<T_TOK, 256>>>(out);                                          // 5
}

// round 15
// speedup vs baseline: 1.1588x; 1.0682x over previous
#include <cuda_runtime.h>
#include <cuda_fp16.h>
#include <math.h>
#include <stdint.h>

#define T_TOK     8192
#define DMODEL    1024
#define DFF       4096
#define E_ROUTED  7
#define TOPK      2
#define CAPACITY  2926
#define WPER      ((size_t)DMODEL * DFF)

// ---------------- scratch ----------------
__device__ __half g_ht[(size_t)T_TOK * DMODEL];
__device__ int    g_topidx[T_TOK * TOPK];
__device__ float  g_gate[T_TOK * TOPK];
__device__ int    g_pos[TOPK * T_TOK];
__device__ int    g_slot_token[E_ROUTED * CAPACITY];
__device__ int    g_count[E_ROUTED];
__device__ __half g_w1t[8 * WPER];                       // [e][F][D] K-major fp16
__device__ __half g_w3t[8 * WPER];
__device__ __half g_w2t[8 * WPER];                       // [e][D][F] K-major fp16
__device__ __half g_ub [(size_t)E_ROUTED * CAPACITY * DFF];
__device__ __half g_ubs[(size_t)T_TOK * DFF];
__device__ float  g_ye [(size_t)E_ROUTED * CAPACITY * DMODEL];
__device__ float  g_ys [(size_t)T_TOK * DMODEL];

// ---------------- helpers ----------------
__device__ __forceinline__ uint32_t smem_u32(const void* p) {
    return (uint32_t)__cvta_generic_to_shared(p);
}
__device__ __forceinline__ void cp16(uint32_t d, const void* s) {
    asm volatile("cp.async.cg.shared.global [%0], [%1], 16;" :: "r"(d), "l"(s) : "memory");
}
__device__ __forceinline__ void cp_commit() {
    asm volatile("cp.async.commit_group;" ::: "memory");
}
template <int N>
__device__ __forceinline__ void cp_wait() {
    asm volatile("cp.async.wait_group %0;" :: "n"(N) : "memory");
}
__device__ __forceinline__ void mma_f16(float c[4], uint32_t a0, uint32_t a1,
                                        uint32_t a2, uint32_t a3,
                                        uint32_t b0, uint32_t b1) {
    asm volatile(
        "mma.sync.aligned.m16n8k16.row.col.f32.f16.f16.f32 "
        "{%0,%1,%2,%3},{%4,%5,%6,%7},{%8,%9},{%0,%1,%2,%3};"
        : "+f"(c[0]), "+f"(c[1]), "+f"(c[2]), "+f"(c[3])
        : "r"(a0), "r"(a1), "r"(a2), "r"(a3), "r"(b0), "r"(b1));
}
__device__ __forceinline__ float silu_f(float v) { return v / (1.0f + __expf(-v)); }

// ---------------- 0) Fused LayerNorm + Router ----------------
__device__ __forceinline__ float blockReduceSum256(float v, float* sh8) {
    int lane = threadIdx.x & 31, wid = threadIdx.x >> 5;
    #pragma unroll
    for (int o = 16; o; o >>= 1) v += __shfl_down_sync(0xffffffffu, v, o);
    if (lane == 0) sh8[wid] = v;
    __syncthreads();
    float r = (threadIdx.x < 8) ? sh8[threadIdx.x] : 0.0f;
    if (wid == 0) {
        #pragma unroll
        for (int o = 4; o; o >>= 1) r += __shfl_down_sync(0xffffffffu, r, o);
        if (lane == 0) sh8[0] = r;
    }
    __syncthreads();
    float res = sh8[0];
    __syncthreads();
    return res;
}

__global__ void ln_router_kernel(const float* __restrict__ x,
                                 const float* __restrict__ gamma,
                                 const float* __restrict__ beta,
                                 const float* __restrict__ Wr) {
    __shared__ float sh[8];
    __shared__ double shd[8][E_ROUTED];
    int t = blockIdx.x, d4 = threadIdx.x;
    int lane = threadIdx.x & 31, wid = threadIdx.x >> 5;
    float4 v = reinterpret_cast<const float4*>(x + (size_t)t * DMODEL)[d4];
    float mu = blockReduceSum256(v.x + v.y + v.z + v.w, sh) * (1.0f / DMODEL);
    float dx = v.x - mu, dy = v.y - mu, dz = v.z - mu, dw = v.w - mu;
    float var = blockReduceSum256(dx*dx + dy*dy + dz*dz + dw*dw, sh) * (1.0f / DMODEL);
    float inv = rsqrtf(var + 1e-5f);
    float4 gg = reinterpret_cast<const float4*>(gamma)[d4];
    float4 bb = reinterpret_cast<const float4*>(beta)[d4];
    float4 o;
    o.x = dx*inv*gg.x + bb.x; o.y = dy*inv*gg.y + bb.y;
    o.z = dz*inv*gg.z + bb.z; o.w = dw*inv*gg.w + bb.w;
    __half2* hrow = reinterpret_cast<__half2*>(g_ht + (size_t)t * DMODEL);
    hrow[d4*2+0] = __floats2half2_rn(o.x, o.y);
    hrow[d4*2+1] = __floats2half2_rn(o.z, o.w);

    const int d0 = d4 * 4;
    double acc[E_ROUTED];
    #pragma unroll
    for (int e = 0; e < E_ROUTED; e++) {
        acc[e] = (double)o.x * (double)Wr[(size_t)(d0+0)*E_ROUTED + e]
               + (double)o.y * (double)Wr[(size_t)(d0+1)*E_ROUTED + e]
               + (double)o.z * (double)Wr[(size_t)(d0+2)*E_ROUTED + e]
               + (double)o.w * (double)Wr[(size_t)(d0+3)*E_ROUTED + e];
    }
    #pragma unroll
    for (int e = 0; e < E_ROUTED; e++)
        #pragma unroll
        for (int off = 16; off; off >>= 1)
            acc[e] += __shfl_down_sync(0xffffffffu, acc[e], off);
    if (lane == 0)
        #pragma unroll
        for (int e = 0; e < E_ROUTED; e++) shd[wid][e] = acc[e];
    __syncthreads();
    if (threadIdx.x == 0) {
        float vv[E_ROUTED];
        #pragma unroll
        for (int e = 0; e < E_ROUTED; e++) {
            double s = 0.0;
            #pragma unroll
            for (int w = 0; w < 8; w++) s += shd[w][e];
            vv[e] = (float)s;
        }
        int i1 = 0;
        #pragma unroll
        for (int e = 1; e < E_ROUTED; e++) if (vv[e] > vv[i1]) i1 = e;
        int i2 = -1;
        #pragma unroll
        for (int e = 0; e < E_ROUTED; e++) {
            if (e == i1) continue;
            if (i2 < 0 || vv[e] > vv[i2]) i2 = e;
        }
        float m = vv[i1], e1 = expf(vv[i1]-m), e2 = expf(vv[i2]-m), invs = 1.0f/(e1+e2);
        g_topidx[t*2+0] = i1; g_topidx[t*2+1] = i2;
        g_gate[t*2+0] = e1*invs; g_gate[t*2+1] = e2*invs;
    }
}

// ---------------- 1) Transpose + fp16-convert, 64x64 tiles ----------------
__global__ void transpose_all(const float* __restrict__ W1, const float* __restrict__ W1s,
                              const float* __restrict__ W3, const float* __restrict__ W3s,
                              const float* __restrict__ W2, const float* __restrict__ W2s) {
    __shared__ float t[64][65];
    int z = blockIdx.z, which = z >> 3, e = z & 7;
    int R = (which < 2) ? DMODEL : DFF;
    int C = (which < 2) ? DFF : DMODEL;
    const float* rsrc = (which == 0) ? W1 : (which == 1) ? W3 : W2;
    const float* ssrc = (which == 0) ? W1s : (which == 1) ? W3s : W2s;
    const float* s = (e < E_ROUTED) ? rsrc + (size_t)e * WPER : ssrc;
    __half* d = ((which == 0) ? g_w1t : (which == 1) ? g_w3t : g_w2t) + (size_t)e * WPER;
    int rt = (which < 2) ? blockIdx.y : blockIdx.x;   // R/64 tiles
    int ct = (which < 2) ? blockIdx.x : blockIdx.y;   // C/64 tiles
    int tx = threadIdx.x & 63, ty = threadIdx.x >> 6;  // 256 thr: 64 x 4
    #pragma unroll
    for (int i = 0; i < 64; i += 4)
        t[ty + i][tx] = s[(size_t)(rt*64 + ty + i) * C + ct*64 + tx];
    __syncthreads();
    #pragma unroll
    for (int i = 0; i < 64; i += 4)
        d[(size_t)(ct*64 + ty + i) * R + rt*64 + tx] = __float2half(t[tx][ty + i]);
}

// ---------------- 2) Dispatch positions ----------------
__global__ void pos_kernel() {
    int e = blockIdx.x;
    __shared__ int warpTot[8];
    int lane = threadIdx.x & 31, wid = threadIdx.x >> 5;
    int running = 0;
    for (int k = 0; k < TOPK; k++)
        for (int base = 0; base < T_TOK; base += 256) {
            int t = base + threadIdx.x;
            int match = (g_topidx[t*2+k] == e) ? 1 : 0;
            unsigned bal = __ballot_sync(0xffffffffu, match);
            int wpre = __popc(bal & ((1u << lane) - 1u));
            if (lane == 31) warpTot[wid] = wpre + match;
            __syncthreads();
            int wbase = 0;
            #pragma unroll
            for (int w = 0; w < 8; w++) if (w < wid) wbase += warpTot[w];
            if (match) {
                int p = running + wbase + wpre;
                if (p < CAPACITY) { g_pos[k*T_TOK+t] = p; g_slot_token[e*CAPACITY+p] = t; }
                else g_pos[k*T_TOK+t] = -1;
            }
            int tot = 0;
            #pragma unroll
            for (int w = 0; w < 8; w++) tot += warpTot[w];
            running += tot;
            __syncthreads();
        }
    if (threadIdx.x == 0) g_count[e] = (running < CAPACITY) ? running : CAPACITY;
}

// ================= 3) Fused W1+W3 fp16 mma GEMM + SwiGLU (R10 exact) =======
#define LDH 40                           // halfs per row (80 B)
#define G13_A_B   (128*LDH*2)            // 10240 B
#define G13_B1_O  G13_A_B
#define G13_B3_O  (G13_A_B + 64*LDH*2)
#define G13_STGB  (G13_A_B + 2*64*LDH*2) // 20480 B
#define G13_SMEM  (5 * G13_STGB)         // 102400 B

__global__ void __launch_bounds__(256, 2) gemm13_mma() {
    extern __shared__ char smB[];
    const int e = blockIdx.z;
    const int n0 = blockIdx.x * 64;
    const int m0 = blockIdx.y * 128;
    const int cnt = (e < E_ROUTED) ? g_count[e] : T_TOK;
    if (m0 >= cnt) return;
    const int tid = threadIdx.x, wid = tid >> 5, lane = tid & 31;
    const int wm = wid >> 1, wn = wid & 1;
    const int gid = lane >> 2, t4 = lane & 3;

    const __half* w1e = g_w1t + (size_t)e * WPER;
    const __half* w3e = g_w3t + (size_t)e * WPER;

    const __half* agh[2]; uint32_t aoffB[2];
    #pragma unroll
    for (int i = 0; i < 2; i++) {
        int idx = tid + i*256;
        int r = idx >> 2, c = idx & 3;
        int mg = m0 + r;
        int tok = (e < E_ROUTED) ? ((mg < cnt) ? g_slot_token[e*CAPACITY + mg] : 0) : mg;
        agh[i] = g_ht + (size_t)tok * DMODEL + c*8;
        aoffB[i] = (uint32_t)(r*80 + c*16);
    }
    const __half* b1gh; const __half* b3gh; uint32_t boffB;
    {
        int n = tid >> 2, c = tid & 3;
        b1gh = w1e + (size_t)(n0 + n) * DMODEL + c*8;
        b3gh = w3e + (size_t)(n0 + n) * DMODEL + c*8;
        boffB = (uint32_t)(n*80 + c*16);
    }
    const uint32_t sbase = smem_u32(smB);

    float c1[2][4][4] = {};
    float c3[2][4][4] = {};

    auto load_stage = [&](int s, int j) {
        uint32_t st = sbase + (uint32_t)s * G13_STGB;
        cp16(st + aoffB[0], agh[0] + j*32);
        cp16(st + aoffB[1], agh[1] + j*32);
        cp16(st + G13_B1_O + boffB, b1gh + j*32);
        cp16(st + G13_B3_O + boffB, b3gh + j*32);
        cp_commit();
    };
    auto compute = [&](int s) {
        const char* stage = smB + s * G13_STGB;
        const uint32_t* A  = (const uint32_t*)(stage) + (wm*32)*20;
        const uint32_t* B1 = (const uint32_t*)(stage + G13_B1_O) + (wn*32)*20;
        const uint32_t* B3 = (const uint32_t*)(stage + G13_B3_O) + (wn*32)*20;
        #pragma unroll
        for (int ks = 0; ks < 2; ks++) {
            const int kb = ks*8 + t4;
            uint32_t a[2][4];
            #pragma unroll
            for (int t = 0; t < 2; t++) {
                int r = t*16 + gid;
                a[t][0] = A[r*20 + kb];
                a[t][1] = A[(r+8)*20 + kb];
                a[t][2] = A[r*20 + kb + 4];
                a[t][3] = A[(r+8)*20 + kb + 4];
            }
            #pragma unroll
            for (int u = 0; u < 4; u++) {
                const int nr = (u*8 + gid)*20;
                uint32_t p0 = B1[nr + kb], p1 = B1[nr + kb + 4];
                uint32_t q0 = B3[nr + kb], q1 = B3[nr + kb + 4];
                #pragma unroll
                for (int t = 0; t < 2; t++) {
                    mma_f16(c1[t][u], a[t][0], a[t][1], a[t][2], a[t][3], p0, p1);
                    mma_f16(c3[t][u], a[t][0], a[t][1], a[t][2], a[t][3], q0, q1);
                }
            }
        }
    };

    const int nch = DMODEL/32;   // 32 (even)
    load_stage(0, 0); load_stage(1, 1); load_stage(2, 2);
    int s = 0;
    #pragma unroll 1
    for (int j = 0; j < nch; j += 2) {
        if (j < nch - 2) cp_wait<1>();
        else             cp_wait<0>();   // TAIL pair
        __syncthreads();
        int s1 = s + 1; if (s1 >= 5) s1 -= 5;
        compute(s);
        compute(s1);
        if (j + 3 < nch) { int s3 = s + 3; if (s3 >= 5) s3 -= 5; load_stage(s3, j + 3); }
        if (j + 4 < nch) { int s4 = s + 4; if (s4 >= 5) s4 -= 5; load_stage(s4, j + 4); }
        s += 2; if (s >= 5) s -= 5;
    }

    __half* dstb = (e < E_ROUTED) ? g_ub + (size_t)e * CAPACITY * DFF : g_ubs;
    #pragma unroll
    for (int t = 0; t < 2; t++)
        #pragma unroll
        for (int half = 0; half < 2; half++) {
            int r = m0 + wm*32 + t*16 + gid + half*8;
            if (r < cnt) {
                __half* drow = dstb + (size_t)r * DFF + n0 + wn*32 + t4*2;
                #pragma unroll
                for (int u = 0; u < 4; u++) {
                    int ci = half*2;
                    float ux = silu_f(c1[t][u][ci])   * c3[t][u][ci];
                    float uy = silu_f(c1[t][u][ci+1]) * c3[t][u][ci+1];
                    *reinterpret_cast<__half2*>(drow + u*8) = __floats2half2_rn(ux, uy);
                }
            }
        }
}

// ================= 4) W2 fp16 mma GEMM (R10 exact) =================
#define G2_A_B  (128*LDH*2)              // 10240 B
#define G2_B_O  G2_A_B
#define G2_STGB (2 * G2_A_B)             // 20480 B
#define G2_SMEM (5 * G2_STGB)            // 102400 B

__global__ void __launch_bounds__(256, 2) gemm2_mma() {
    extern __shared__ char smB[];
    const int e = blockIdx.z;
    const int n0 = blockIdx.x * 128;
    const int m0 = blockIdx.y * 128;
    const int cnt = (e < E_ROUTED) ? g_count[e] : T_TOK;
    if (m0 >= cnt) return;
    const int tid = threadIdx.x, wid = tid >> 5, lane = tid & 31;
    const int wm = wid >> 1, wn = wid & 1;
    const int gid = lane >> 2, t4 = lane & 3;

    const __half* Abase = (e < E_ROUTED) ? g_ub + (size_t)e * CAPACITY * DFF : g_ubs;
    const __half* w2e = g_w2t + (size_t)e * WPER;

    const __half* agh[2]; uint32_t aoffB[2];
    #pragma unroll
    for (int i = 0; i < 2; i++) {
        int idx = tid + i*256;
        int r = idx >> 2, c = idx & 3;
        int mg = m0 + r;
        agh[i] = Abase + (size_t)((mg < cnt) ? mg : 0) * DFF + c*8;
        aoffB[i] = (uint32_t)(r*80 + c*16);
    }
    const __half* bgh[2]; uint32_t boffB[2];
    #pragma unroll
    for (int i = 0; i < 2; i++) {
        int idx = tid + i*256;
        int n = idx >> 2, c = idx & 3;
        bgh[i] = w2e + (size_t)(n0 + n) * DFF + c*8;
        boffB[i] = (uint32_t)(n*80 + c*16);
    }
    const uint32_t sbase = smem_u32(smB);

    float cc[2][8][4] = {};

    auto load_stage = [&](int s, int j) {
        uint32_t st = sbase + (uint32_t)s * G2_STGB;
        cp16(st + aoffB[0], agh[0] + j*32);
        cp16(st + aoffB[1], agh[1] + j*32);
        cp16(st + G2_B_O + boffB[0], bgh[0] + j*32);
        cp16(st + G2_B_O + boffB[1], bgh[1] + j*32);
        cp_commit();
    };
    auto compute = [&](int s) {
        const char* stage = smB + s * G2_STGB;
        const uint32_t* A = (const uint32_t*)(stage) + (wm*32)*20;
        const uint32_t* B = (const uint32_t*)(stage + G2_B_O) + (wn*64)*20;
        #pragma unroll
        for (int ks = 0; ks < 2; ks++) {
            const int kb = ks*8 + t4;
            uint32_t a[2][4];
            #pragma unroll
            for (int t = 0; t < 2; t++) {
                int r = t*16 + gid;
                a[t][0] = A[r*20 + kb];
                a[t][1] = A[(r+8)*20 + kb];
                a[t][2] = A[r*20 + kb + 4];
                a[t][3] = A[(r+8)*20 + kb + 4];
            }
            #pragma unroll
            for (int u = 0; u < 8; u++) {
                const int nr = (u*8 + gid)*20;
                uint32_t b0 = B[nr + kb], b1 = B[nr + kb + 4];
                #pragma unroll
                for (int t = 0; t < 2; t++)
                    mma_f16(cc[t][u], a[t][0], a[t][1], a[t][2], a[t][3], b0, b1);
            }
        }
    };

    const int nch = DFF/32;   // 128 (even)
    load_stage(0, 0); load_stage(1, 1); load_stage(2, 2);
    int s = 0;
    #pragma unroll 1
    for (int j = 0; j < nch; j += 2) {
        if (j < nch - 2) cp_wait<1>();
        else             cp_wait<0>();   // TAIL pair
        __syncthreads();
        int s1 = s + 1; if (s1 >= 5) s1 -= 5;
        compute(s);
        compute(s1);
        if (j + 3 < nch) { int s3 = s + 3; if (s3 >= 5) s3 -= 5; load_stage(s3, j + 3); }
        if (j + 4 < nch) { int s4 = s + 4; if (s4 >= 5) s4 -= 5; load_stage(s4, j + 4); }
        s += 2; if (s >= 5) s -= 5;
    }

    float* dstb = (e < E_ROUTED) ? g_ye + (size_t)e * CAPACITY * DMODEL : g_ys;
    #pragma unroll
    for (int t = 0; t < 2; t++)
        #pragma unroll
        for (int half = 0; half < 2; half++) {
            int r = m0 + wm*32 + t*16 + gid + half*8;
            if (r < cnt) {
                float* drow = dstb + (size_t)r * DMODEL + n0 + wn*64 + t4*2;
                #pragma unroll
                for (int u = 0; u < 8; u++) {
                    int ci = half*2;
                    float2 o; o.x = cc[t][u][ci]; o.y = cc[t][u][ci+1];
                    *reinterpret_cast<float2*>(drow + u*8) = o;
                }
            }
        }
}

// ---------------- 5) Combine ----------------
__global__ void combine_kernel(float* __restrict__ out) {
    int t = blockIdx.x, d4 = threadIdx.x;
    float4 o = reinterpret_cast<const float4*>(g_ys + (size_t)t * DMODEL)[d4];
    #pragma unroll
    for (int k = 0; k < TOPK; k++) {
        int p = g_pos[k * T_TOK + t];
        if (p >= 0) {
            int e = g_topidx[t*2+k];
            float gv = g_gate[t*2+k];
            float4 y = reinterpret_cast<const float4*>(g_ye + ((size_t)e*CAPACITY + p) * DMODEL)[d4];
            o.x += gv*y.x; o.y += gv*y.y; o.z += gv*y.z; o.w += gv*y.w;
        }
    }
    reinterpret_cast<float4*>(out + (size_t)t * DMODEL)[d4] = o;
}

// ---------------- launch ----------------
extern "C" void kernel_launch(void* const* d_in, const int* in_sizes, int n_in,
                              void* d_out, int out_size) {
    (void)in_sizes; (void)n_in; (void)out_size;
    const float* x    = (const float*)d_in[0];
    const float* ln_g = (const float*)d_in[1];
    const float* ln_b = (const float*)d_in[2];
    const float* Wr   = (const float*)d_in[3];
    const float* W1   = (const float*)d_in[4];
    const float* W3   = (const float*)d_in[5];
    const float* W2   = (const float*)d_in[6];
    const float* W1s  = (const float*)d_in[7];
    const float* W3s  = (const float*)d_in[8];
    const float* W2s  = (const float*)d_in[9];
    float* out = (float*)d_out;

    cudaFuncSetAttribute(gemm13_mma, cudaFuncAttributeMaxDynamicSharedMemorySize, G13_SMEM);
    cudaFuncSetAttribute(gemm2_mma,  cudaFuncAttributeMaxDynamicSharedMemorySize, G2_SMEM);

    ln_router_kernel<<<T_TOK, 256>>>(x, ln_g, ln_b, Wr);                          // 0
    transpose_all<<<dim3(64, 16, 24), 256>>>(W1, W1s, W3, W3s, W2, W2s);          // 1
    pos_kernel<<<E_ROUTED, 256>>>();                                              // 2
    gemm13_mma<<<dim3(DFF/64, T_TOK/128, E_ROUTED + 1), 256, G13_SMEM>>>();       // 3 <- ncu slot
    gemm2_mma <<<dim3(DMODEL/128, T_TOK/128, E_ROUTED + 1), 256, G2_SMEM>>>();    // 4
    combine_kernel<<<T_TOK, 256>>>(out);                                          // 5
}

// round 16
// speedup vs baseline: 1.1592x; 1.0004x over previous
#include <cuda_runtime.h>
#include <cuda_fp16.h>
#include <math.h>
#include <stdint.h>

#define T_TOK     8192
#define DMODEL    1024
#define DFF       4096
#define E_ROUTED  7
#define TOPK      2
#define CAPACITY  2926
#define WPER      ((size_t)DMODEL * DFF)
#define TRBLKS    24576                  // 24 * 64 * 16 transpose blocks

// ---------------- scratch ----------------
__device__ __half g_ht[(size_t)T_TOK * DMODEL];
__device__ int    g_topidx[T_TOK * TOPK];
__device__ float  g_gate[T_TOK * TOPK];
__device__ int    g_pos[TOPK * T_TOK];
__device__ int    g_slot_token[E_ROUTED * CAPACITY];
__device__ int    g_count[E_ROUTED];
__device__ __half g_w1t[8 * WPER];                       // [e][F][D] K-major fp16
__device__ __half g_w3t[8 * WPER];
__device__ __half g_w2t[8 * WPER];                       // [e][D][F] K-major fp16
__device__ __half g_ub [(size_t)E_ROUTED * CAPACITY * DFF];
__device__ __half g_ubs[(size_t)T_TOK * DFF];
__device__ __half g_ye [(size_t)E_ROUTED * CAPACITY * DMODEL];   // fp16 now
__device__ __half g_ys [(size_t)T_TOK * DMODEL];                 // fp16 now

// ---------------- helpers ----------------
__device__ __forceinline__ uint32_t smem_u32(const void* p) {
    return (uint32_t)__cvta_generic_to_shared(p);
}
__device__ __forceinline__ void cp16(uint32_t d, const void* s) {
    asm volatile("cp.async.cg.shared.global [%0], [%1], 16;" :: "r"(d), "l"(s) : "memory");
}
__device__ __forceinline__ void cp_commit() {
    asm volatile("cp.async.commit_group;" ::: "memory");
}
template <int N>
__device__ __forceinline__ void cp_wait() {
    asm volatile("cp.async.wait_group %0;" :: "n"(N) : "memory");
}
__device__ __forceinline__ void mma_f16(float c[4], uint32_t a0, uint32_t a1,
                                        uint32_t a2, uint32_t a3,
                                        uint32_t b0, uint32_t b1) {
    asm volatile(
        "mma.sync.aligned.m16n8k16.row.col.f32.f16.f16.f32 "
        "{%0,%1,%2,%3},{%4,%5,%6,%7},{%8,%9},{%0,%1,%2,%3};"
        : "+f"(c[0]), "+f"(c[1]), "+f"(c[2]), "+f"(c[3])
        : "r"(a0), "r"(a1), "r"(a2), "r"(a3), "r"(b0), "r"(b1));
}
__device__ __forceinline__ float silu_f(float v) { return v / (1.0f + __expf(-v)); }

// ---------------- 0) Fused prep: transpose (blocks < TRBLKS) + LN/router ----
__device__ __forceinline__ float blockReduceSum256(float v, float* sh8) {
    int lane = threadIdx.x & 31, wid = threadIdx.x >> 5;
    #pragma unroll
    for (int o = 16; o; o >>= 1) v += __shfl_down_sync(0xffffffffu, v, o);
    if (lane == 0) sh8[wid] = v;
    __syncthreads();
    float r = (threadIdx.x < 8) ? sh8[threadIdx.x] : 0.0f;
    if (wid == 0) {
        #pragma unroll
        for (int o = 4; o; o >>= 1) r += __shfl_down_sync(0xffffffffu, r, o);
        if (lane == 0) sh8[0] = r;
    }
    __syncthreads();
    float res = sh8[0];
    __syncthreads();
    return res;
}

__global__ void prep_kernel(const float* __restrict__ x,
                            const float* __restrict__ gamma,
                            const float* __restrict__ beta,
                            const float* __restrict__ Wr,
                            const float* __restrict__ W1, const float* __restrict__ W1s,
                            const float* __restrict__ W3, const float* __restrict__ W3s,
                            const float* __restrict__ W2, const float* __restrict__ W2s) {
    __shared__ float tbuf[64][65];
    __shared__ float sh[8];
    __shared__ double shd[8][E_ROUTED];

    if (blockIdx.x < TRBLKS) {
        // ---------------- transpose + fp16 convert, 64x64 tile ----------------
        int z = blockIdx.x >> 10;              // 0..23
        int rem = blockIdx.x & 1023;
        int bx = rem & 63, by = rem >> 6;      // bx 0..63, by 0..15
        int which = z >> 3, e = z & 7;
        int R = (which < 2) ? DMODEL : DFF;
        int C = (which < 2) ? DFF : DMODEL;
        const float* rsrc = (which == 0) ? W1 : (which == 1) ? W3 : W2;
        const float* ssrc = (which == 0) ? W1s : (which == 1) ? W3s : W2s;
        const float* s = (e < E_ROUTED) ? rsrc + (size_t)e * WPER : ssrc;
        __half* d = ((which == 0) ? g_w1t : (which == 1) ? g_w3t : g_w2t) + (size_t)e * WPER;
        int rt = (which < 2) ? by : bx;
        int ct = (which < 2) ? bx : by;
        int tx = threadIdx.x & 63, ty = threadIdx.x >> 6;
        #pragma unroll
        for (int i = 0; i < 64; i += 4)
            tbuf[ty + i][tx] = s[(size_t)(rt*64 + ty + i) * C + ct*64 + tx];
        __syncthreads();
        #pragma unroll
        for (int i = 0; i < 64; i += 4)
            d[(size_t)(ct*64 + ty + i) * R + rt*64 + tx] = __float2half(tbuf[tx][ty + i]);
        return;
    }

    // ---------------- LayerNorm + router ----------------
    int t = blockIdx.x - TRBLKS, d4 = threadIdx.x;
    int lane = threadIdx.x & 31, wid = threadIdx.x >> 5;
    float4 v = reinterpret_cast<const float4*>(x + (size_t)t * DMODEL)[d4];
    float mu = blockReduceSum256(v.x + v.y + v.z + v.w, sh) * (1.0f / DMODEL);
    float dx = v.x - mu, dy = v.y - mu, dz = v.z - mu, dw = v.w - mu;
    float var = blockReduceSum256(dx*dx + dy*dy + dz*dz + dw*dw, sh) * (1.0f / DMODEL);
    float inv = rsqrtf(var + 1e-5f);
    float4 gg = reinterpret_cast<const float4*>(gamma)[d4];
    float4 bb = reinterpret_cast<const float4*>(beta)[d4];
    float4 o;
    o.x = dx*inv*gg.x + bb.x; o.y = dy*inv*gg.y + bb.y;
    o.z = dz*inv*gg.z + bb.z; o.w = dw*inv*gg.w + bb.w;
    __half2* hrow = reinterpret_cast<__half2*>(g_ht + (size_t)t * DMODEL);
    hrow[d4*2+0] = __floats2half2_rn(o.x, o.y);
    hrow[d4*2+1] = __floats2half2_rn(o.z, o.w);

    const int d0 = d4 * 4;
    double acc[E_ROUTED];
    #pragma unroll
    for (int e = 0; e < E_ROUTED; e++) {
        acc[e] = (double)o.x * (double)Wr[(size_t)(d0+0)*E_ROUTED + e]
               + (double)o.y * (double)Wr[(size_t)(d0+1)*E_ROUTED + e]
               + (double)o.z * (double)Wr[(size_t)(d0+2)*E_ROUTED + e]
               + (double)o.w * (double)Wr[(size_t)(d0+3)*E_ROUTED + e];
    }
    #pragma unroll
    for (int e = 0; e < E_ROUTED; e++)
        #pragma unroll
        for (int off = 16; off; off >>= 1)
            acc[e] += __shfl_down_sync(0xffffffffu, acc[e], off);
    if (lane == 0)
        #pragma unroll
        for (int e = 0; e < E_ROUTED; e++) shd[wid][e] = acc[e];
    __syncthreads();
    if (threadIdx.x == 0) {
        float vv[E_ROUTED];
        #pragma unroll
        for (int e = 0; e < E_ROUTED; e++) {
            double s = 0.0;
            #pragma unroll
            for (int w = 0; w < 8; w++) s += shd[w][e];
            vv[e] = (float)s;
        }
        int i1 = 0;
        #pragma unroll
        for (int e = 1; e < E_ROUTED; e++) if (vv[e] > vv[i1]) i1 = e;
        int i2 = -1;
        #pragma unroll
        for (int e = 0; e < E_ROUTED; e++) {
            if (e == i1) continue;
            if (i2 < 0 || vv[e] > vv[i2]) i2 = e;
        }
        float m = vv[i1], e1 = expf(vv[i1]-m), e2 = expf(vv[i2]-m), invs = 1.0f/(e1+e2);
        g_topidx[t*2+0] = i1; g_topidx[t*2+1] = i2;
        g_gate[t*2+0] = e1*invs; g_gate[t*2+1] = e2*invs;
    }
}

// ---------------- 1) Dispatch positions ----------------
__global__ void pos_kernel() {
    int e = blockIdx.x;
    __shared__ int warpTot[8];
    int lane = threadIdx.x & 31, wid = threadIdx.x >> 5;
    int running = 0;
    for (int k = 0; k < TOPK; k++)
        for (int base = 0; base < T_TOK; base += 256) {
            int t = base + threadIdx.x;
            int match = (g_topidx[t*2+k] == e) ? 1 : 0;
            unsigned bal = __ballot_sync(0xffffffffu, match);
            int wpre = __popc(bal & ((1u << lane) - 1u));
            if (lane == 31) warpTot[wid] = wpre + match;
            __syncthreads();
            int wbase = 0;
            #pragma unroll
            for (int w = 0; w < 8; w++) if (w < wid) wbase += warpTot[w];
            if (match) {
                int p = running + wbase + wpre;
                if (p < CAPACITY) { g_pos[k*T_TOK+t] = p; g_slot_token[e*CAPACITY+p] = t; }
                else g_pos[k*T_TOK+t] = -1;
            }
            int tot = 0;
            #pragma unroll
            for (int w = 0; w < 8; w++) tot += warpTot[w];
            running += tot;
            __syncthreads();
        }
    if (threadIdx.x == 0) g_count[e] = (running < CAPACITY) ? running : CAPACITY;
}

// ================= 2) Fused W1+W3 fp16 mma GEMM + SwiGLU (R10/R15 exact) ===
#define LDH 40
#define G13_A_B   (128*LDH*2)
#define G13_B1_O  G13_A_B
#define G13_B3_O  (G13_A_B + 64*LDH*2)
#define G13_STGB  (G13_A_B + 2*64*LDH*2)
#define G13_SMEM  (5 * G13_STGB)

__global__ void __launch_bounds__(256, 2) gemm13_mma() {
    extern __shared__ char smB[];
    const int e = blockIdx.z;
    const int n0 = blockIdx.x * 64;
    const int m0 = blockIdx.y * 128;
    const int cnt = (e < E_ROUTED) ? g_count[e] : T_TOK;
    if (m0 >= cnt) return;
    const int tid = threadIdx.x, wid = tid >> 5, lane = tid & 31;
    const int wm = wid >> 1, wn = wid & 1;
    const int gid = lane >> 2, t4 = lane & 3;

    const __half* w1e = g_w1t + (size_t)e * WPER;
    const __half* w3e = g_w3t + (size_t)e * WPER;

    const __half* agh[2]; uint32_t aoffB[2];
    #pragma unroll
    for (int i = 0; i < 2; i++) {
        int idx = tid + i*256;
        int r = idx >> 2, c = idx & 3;
        int mg = m0 + r;
        int tok = (e < E_ROUTED) ? ((mg < cnt) ? g_slot_token[e*CAPACITY + mg] : 0) : mg;
        agh[i] = g_ht + (size_t)tok * DMODEL + c*8;
        aoffB[i] = (uint32_t)(r*80 + c*16);
    }
    const __half* b1gh; const __half* b3gh; uint32_t boffB;
    {
        int n = tid >> 2, c = tid & 3;
        b1gh = w1e + (size_t)(n0 + n) * DMODEL + c*8;
        b3gh = w3e + (size_t)(n0 + n) * DMODEL + c*8;
        boffB = (uint32_t)(n*80 + c*16);
    }
    const uint32_t sbase = smem_u32(smB);

    float c1[2][4][4] = {};
    float c3[2][4][4] = {};

    auto load_stage = [&](int s, int j) {
        uint32_t st = sbase + (uint32_t)s * G13_STGB;
        cp16(st + aoffB[0], agh[0] + j*32);
        cp16(st + aoffB[1], agh[1] + j*32);
        cp16(st + G13_B1_O + boffB, b1gh + j*32);
        cp16(st + G13_B3_O + boffB, b3gh + j*32);
        cp_commit();
    };
    auto compute = [&](int s) {
        const char* stage = smB + s * G13_STGB;
        const uint32_t* A  = (const uint32_t*)(stage) + (wm*32)*20;
        const uint32_t* B1 = (const uint32_t*)(stage + G13_B1_O) + (wn*32)*20;
        const uint32_t* B3 = (const uint32_t*)(stage + G13_B3_O) + (wn*32)*20;
        #pragma unroll
        for (int ks = 0; ks < 2; ks++) {
            const int kb = ks*8 + t4;
            uint32_t a[2][4];
            #pragma unroll
            for (int t = 0; t < 2; t++) {
                int r = t*16 + gid;
                a[t][0] = A[r*20 + kb];
                a[t][1] = A[(r+8)*20 + kb];
                a[t][2] = A[r*20 + kb + 4];
                a[t][3] = A[(r+8)*20 + kb + 4];
            }
            #pragma unroll
            for (int u = 0; u < 4; u++) {
                const int nr = (u*8 + gid)*20;
                uint32_t p0 = B1[nr + kb], p1 = B1[nr + kb + 4];
                uint32_t q0 = B3[nr + kb], q1 = B3[nr + kb + 4];
                #pragma unroll
                for (int t = 0; t < 2; t++) {
                    mma_f16(c1[t][u], a[t][0], a[t][1], a[t][2], a[t][3], p0, p1);
                    mma_f16(c3[t][u], a[t][0], a[t][1], a[t][2], a[t][3], q0, q1);
                }
            }
        }
    };

    const int nch = DMODEL/32;
    load_stage(0, 0); load_stage(1, 1); load_stage(2, 2);
    int s = 0;
    #pragma unroll 1
    for (int j = 0; j < nch; j += 2) {
        if (j < nch - 2) cp_wait<1>();
        else             cp_wait<0>();   // TAIL pair
        __syncthreads();
        int s1 = s + 1; if (s1 >= 5) s1 -= 5;
        compute(s);
        compute(s1);
        if (j + 3 < nch) { int s3 = s + 3; if (s3 >= 5) s3 -= 5; load_stage(s3, j + 3); }
        if (j + 4 < nch) { int s4 = s + 4; if (s4 >= 5) s4 -= 5; load_stage(s4, j + 4); }
        s += 2; if (s >= 5) s -= 5;
    }

    __half* dstb = (e < E_ROUTED) ? g_ub + (size_t)e * CAPACITY * DFF : g_ubs;
    #pragma unroll
    for (int t = 0; t < 2; t++)
        #pragma unroll
        for (int half = 0; half < 2; half++) {
            int r = m0 + wm*32 + t*16 + gid + half*8;
            if (r < cnt) {
                __half* drow = dstb + (size_t)r * DFF + n0 + wn*32 + t4*2;
                #pragma unroll
                for (int u = 0; u < 4; u++) {
                    int ci = half*2;
                    float ux = silu_f(c1[t][u][ci])   * c3[t][u][ci];
                    float uy = silu_f(c1[t][u][ci+1]) * c3[t][u][ci+1];
                    *reinterpret_cast<__half2*>(drow + u*8) = __floats2half2_rn(ux, uy);
                }
            }
        }
}

// ================= 3) W2 fp16 mma GEMM (fp16 output) =================
#define G2_A_B  (128*LDH*2)
#define G2_B_O  G2_A_B
#define G2_STGB (2 * G2_A_B)
#define G2_SMEM (5 * G2_STGB)

__global__ void __launch_bounds__(256, 2) gemm2_mma() {
    extern __shared__ char smB[];
    const int e = blockIdx.z;
    const int n0 = blockIdx.x * 128;
    const int m0 = blockIdx.y * 128;
    const int cnt = (e < E_ROUTED) ? g_count[e] : T_TOK;
    if (m0 >= cnt) return;
    const int tid = threadIdx.x, wid = tid >> 5, lane = tid & 31;
    const int wm = wid >> 1, wn = wid & 1;
    const int gid = lane >> 2, t4 = lane & 3;

    const __half* Abase = (e < E_ROUTED) ? g_ub + (size_t)e * CAPACITY * DFF : g_ubs;
    const __half* w2e = g_w2t + (size_t)e * WPER;

    const __half* agh[2]; uint32_t aoffB[2];
    #pragma unroll
    for (int i = 0; i < 2; i++) {
        int idx = tid + i*256;
        int r = idx >> 2, c = idx & 3;
        int mg = m0 + r;
        agh[i] = Abase + (size_t)((mg < cnt) ? mg : 0) * DFF + c*8;
        aoffB[i] = (uint32_t)(r*80 + c*16);
    }
    const __half* bgh[2]; uint32_t boffB[2];
    #pragma unroll
    for (int i = 0; i < 2; i++) {
        int idx = tid + i*256;
        int n = idx >> 2, c = idx & 3;
        bgh[i] = w2e + (size_t)(n0 + n) * DFF + c*8;
        boffB[i] = (uint32_t)(n*80 + c*16);
    }
    const uint32_t sbase = smem_u32(smB);

    float cc[2][8][4] = {};

    auto load_stage = [&](int s, int j) {
        uint32_t st = sbase + (uint32_t)s * G2_STGB;
        cp16(st + aoffB[0], agh[0] + j*32);
        cp16(st + aoffB[1], agh[1] + j*32);
        cp16(st + G2_B_O + boffB[0], bgh[0] + j*32);
        cp16(st + G2_B_O + boffB[1], bgh[1] + j*32);
        cp_commit();
    };
    auto compute = [&](int s) {
        const char* stage = smB + s * G2_STGB;
        const uint32_t* A = (const uint32_t*)(stage) + (wm*32)*20;
        const uint32_t* B = (const uint32_t*)(stage + G2_B_O) + (wn*64)*20;
        #pragma unroll
        for (int ks = 0; ks < 2; ks++) {
            const int kb = ks*8 + t4;
            uint32_t a[2][4];
            #pragma unroll
            for (int t = 0; t < 2; t++) {
                int r = t*16 + gid;
                a[t][0] = A[r*20 + kb];
                a[t][1] = A[(r+8)*20 + kb];
                a[t][2] = A[r*20 + kb + 4];
                a[t][3] = A[(r+8)*20 + kb + 4];
            }
            #pragma unroll
            for (int u = 0; u < 8; u++) {
                const int nr = (u*8 + gid)*20;
                uint32_t b0 = B[nr + kb], b1 = B[nr + kb + 4];
                #pragma unroll
                for (int t = 0; t < 2; t++)
                    mma_f16(cc[t][u], a[t][0], a[t][1], a[t][2], a[t][3], b0, b1);
            }
        }
    };

    const int nch = DFF/32;
    load_stage(0, 0); load_stage(1, 1); load_stage(2, 2);
    int s = 0;
    #pragma unroll 1
    for (int j = 0; j < nch; j += 2) {
        if (j < nch - 2) cp_wait<1>();
        else             cp_wait<0>();   // TAIL pair
        __syncthreads();
        int s1 = s + 1; if (s1 >= 5) s1 -= 5;
        compute(s);
        compute(s1);
        if (j + 3 < nch) { int s3 = s + 3; if (s3 >= 5) s3 -= 5; load_stage(s3, j + 3); }
        if (j + 4 < nch) { int s4 = s + 4; if (s4 >= 5) s4 -= 5; load_stage(s4, j + 4); }
        s += 2; if (s >= 5) s -= 5;
    }

    __half* dstb = (e < E_ROUTED) ? g_ye + (size_t)e * CAPACITY * DMODEL : g_ys;
    #pragma unroll
    for (int t = 0; t < 2; t++)
        #pragma unroll
        for (int half = 0; half < 2; half++) {
            int r = m0 + wm*32 + t*16 + gid + half*8;
            if (r < cnt) {
                __half* drow = dstb + (size_t)r * DMODEL + n0 + wn*64 + t4*2;
                #pragma unroll
                for (int u = 0; u < 8; u++) {
                    int ci = half*2;
                    *reinterpret_cast<__half2*>(drow + u*8) =
                        __floats2half2_rn(cc[t][u][ci], cc[t][u][ci+1]);
                }
            }
        }
}

// ---------------- 4) Combine (fp16 inputs) ----------------
__global__ void combine_kernel(float* __restrict__ out) {
    int t = blockIdx.x, d4 = threadIdx.x;
    const __half2* ys2 = reinterpret_cast<const __half2*>(g_ys + (size_t)t * DMODEL);
    float2 s0 = __half22float2(ys2[d4*2+0]);
    float2 s1 = __half22float2(ys2[d4*2+1]);
    float4 o;
    o.x = s0.x; o.y = s0.y; o.z = s1.x; o.w = s1.y;
    #pragma unroll
    for (int k = 0; k < TOPK; k++) {
        int p = g_pos[k * T_TOK + t];
        if (p >= 0) {
            int e = g_topidx[t*2+k];
            float gv = g_gate[t*2+k];
            const __half2* y2 = reinterpret_cast<const __half2*>(
                g_ye + ((size_t)e*CAPACITY + p) * DMODEL);
            float2 y0 = __half22float2(y2[d4*2+0]);
            float2 y1 = __half22float2(y2[d4*2+1]);
            o.x += gv*y0.x; o.y += gv*y0.y; o.z += gv*y1.x; o.w += gv*y1.y;
        }
    }
    reinterpret_cast<float4*>(out + (size_t)t * DMODEL)[d4] = o;
}

// ---------------- launch ----------------
extern "C" void kernel_launch(void* const* d_in, const int* in_sizes, int n_in,
                              void* d_out, int out_size) {
    (void)in_sizes; (void)n_in; (void)out_size;
    const float* x    = (const float*)d_in[0];
    const float* ln_g = (const float*)d_in[1];
    const float* ln_b = (const float*)d_in[2];
    const float* Wr   = (const float*)d_in[3];
    const float* W1   = (const float*)d_in[4];
    const float* W3   = (const float*)d_in[5];
    const float* W2   = (const float*)d_in[6];
    const float* W1s  = (const float*)d_in[7];
    const float* W3s  = (const float*)d_in[8];
    const float* W2s  = (const float*)d_in[9];
    float* out = (float*)d_out;

    cudaFuncSetAttribute(gemm13_mma, cudaFuncAttributeMaxDynamicSharedMemorySize, G13_SMEM);
    cudaFuncSetAttribute(gemm2_mma,  cudaFuncAttributeMaxDynamicSharedMemorySize, G2_SMEM);

    prep_kernel<<<TRBLKS + T_TOK, 256>>>(x, ln_g, ln_b, Wr,
                                         W1, W1s, W3, W3s, W2, W2s);              // 0
    pos_kernel<<<E_ROUTED, 256>>>();                                              // 1
    gemm13_mma<<<dim3(DFF/64, T_TOK/128, E_ROUTED + 1), 256, G13_SMEM>>>();       // 2
    gemm2_mma <<<dim3(DMODEL/128, T_TOK/128, E_ROUTED + 1), 256, G2_SMEM>>>();    // 3 <- ncu slot
    combine_kernel<<<T_TOK, 256>>>(out);                                          // 4
}

// round 17
// speedup vs baseline: 1.1597x; 1.0004x over previous
#include <cuda_runtime.h>
#include <cuda_fp16.h>
#include <math.h>
#include <stdint.h>

#define T_TOK     8192
#define DMODEL    1024
#define DFF       4096
#define E_ROUTED  7
#define TOPK      2
#define CAPACITY  2926
#define WPER      ((size_t)DMODEL * DFF)

// ---------------- scratch ----------------
__device__ __half g_ht[(size_t)T_TOK * DMODEL];
__device__ int    g_topidx[T_TOK * TOPK];
__device__ float  g_gate[T_TOK * TOPK];
__device__ int    g_pos[TOPK * T_TOK];
__device__ int    g_slot_token[E_ROUTED * CAPACITY];
__device__ int    g_count[E_ROUTED];
__device__ __half g_w1t[8 * WPER];
__device__ __half g_w3t[8 * WPER];
__device__ __half g_w2t[8 * WPER];
__device__ __half g_ub [(size_t)E_ROUTED * CAPACITY * DFF];
__device__ __half g_ubs[(size_t)T_TOK * DFF];
__device__ __half g_ye [(size_t)E_ROUTED * CAPACITY * DMODEL];
__device__ __half g_ys [(size_t)T_TOK * DMODEL];

// ---------------- helpers ----------------
__device__ __forceinline__ uint32_t smem_u32(const void* p) {
    return (uint32_t)__cvta_generic_to_shared(p);
}
__device__ __forceinline__ void cp16(uint32_t d, const void* s) {
    asm volatile("cp.async.cg.shared.global [%0], [%1], 16;" :: "r"(d), "l"(s) : "memory");
}
__device__ __forceinline__ void cp_commit() {
    asm volatile("cp.async.commit_group;" ::: "memory");
}
template <int N>
__device__ __forceinline__ void cp_wait() {
    asm volatile("cp.async.wait_group %0;" :: "n"(N) : "memory");
}
__device__ __forceinline__ void mma_f16(float c[4], uint32_t a0, uint32_t a1,
                                        uint32_t a2, uint32_t a3,
                                        uint32_t b0, uint32_t b1) {
    asm volatile(
        "mma.sync.aligned.m16n8k16.row.col.f32.f16.f16.f32 "
        "{%0,%1,%2,%3},{%4,%5,%6,%7},{%8,%9},{%0,%1,%2,%3};"
        : "+f"(c[0]), "+f"(c[1]), "+f"(c[2]), "+f"(c[3])
        : "r"(a0), "r"(a1), "r"(a2), "r"(a3), "r"(b0), "r"(b1));
}
__device__ __forceinline__ float silu_f(float v) { return v / (1.0f + __expf(-v)); }

// ---------------- LN + router ----------------
__device__ __forceinline__ float blockReduceSum256(float v, float* sh8) {
    int lane = threadIdx.x & 31, wid = threadIdx.x >> 5;
    #pragma unroll
    for (int o = 16; o; o >>= 1) v += __shfl_down_sync(0xffffffffu, v, o);
    if (lane == 0) sh8[wid] = v;
    __syncthreads();
    float r = (threadIdx.x < 8) ? sh8[threadIdx.x] : 0.0f;
    if (wid == 0) {
        #pragma unroll
        for (int o = 4; o; o >>= 1) r += __shfl_down_sync(0xffffffffu, r, o);
        if (lane == 0) sh8[0] = r;
    }
    __syncthreads();
    float res = sh8[0];
    __syncthreads();
    return res;
}

__global__ void ln_router_kernel(const float* __restrict__ x,
                                 const float* __restrict__ gamma,
                                 const float* __restrict__ beta,
                                 const float* __restrict__ Wr) {
    __shared__ float sh[8];
    __shared__ double shd[8][E_ROUTED];
    int t = blockIdx.x, d4 = threadIdx.x;
    int lane = threadIdx.x & 31, wid = threadIdx.x >> 5;
    float4 v = reinterpret_cast<const float4*>(x + (size_t)t * DMODEL)[d4];
    float mu = blockReduceSum256(v.x + v.y + v.z + v.w, sh) * (1.0f / DMODEL);
    float dx = v.x - mu, dy = v.y - mu, dz = v.z - mu, dw = v.w - mu;
    float var = blockReduceSum256(dx*dx + dy*dy + dz*dz + dw*dw, sh) * (1.0f / DMODEL);
    float inv = rsqrtf(var + 1e-5f);
    float4 gg = reinterpret_cast<const float4*>(gamma)[d4];
    float4 bb = reinterpret_cast<const float4*>(beta)[d4];
    float4 o;
    o.x = dx*inv*gg.x + bb.x; o.y = dy*inv*gg.y + bb.y;
    o.z = dz*inv*gg.z + bb.z; o.w = dw*inv*gg.w + bb.w;
    __half2* hrow = reinterpret_cast<__half2*>(g_ht + (size_t)t * DMODEL);
    hrow[d4*2+0] = __floats2half2_rn(o.x, o.y);
    hrow[d4*2+1] = __floats2half2_rn(o.z, o.w);

    const int d0 = d4 * 4;
    double acc[E_ROUTED];
    #pragma unroll
    for (int e = 0; e < E_ROUTED; e++) {
        acc[e] = (double)o.x * (double)Wr[(size_t)(d0+0)*E_ROUTED + e]
               + (double)o.y * (double)Wr[(size_t)(d0+1)*E_ROUTED + e]
               + (double)o.z * (double)Wr[(size_t)(d0+2)*E_ROUTED + e]
               + (double)o.w * (double)Wr[(size_t)(d0+3)*E_ROUTED + e];
    }
    #pragma unroll
    for (int e = 0; e < E_ROUTED; e++)
        #pragma unroll
        for (int off = 16; off; off >>= 1)
            acc[e] += __shfl_down_sync(0xffffffffu, acc[e], off);
    if (lane == 0)
        #pragma unroll
        for (int e = 0; e < E_ROUTED; e++) shd[wid][e] = acc[e];
    __syncthreads();
    if (threadIdx.x == 0) {
        float vv[E_ROUTED];
        #pragma unroll
        for (int e = 0; e < E_ROUTED; e++) {
            double s = 0.0;
            #pragma unroll
            for (int w = 0; w < 8; w++) s += shd[w][e];
            vv[e] = (float)s;
        }
        int i1 = 0;
        #pragma unroll
        for (int e = 1; e < E_ROUTED; e++) if (vv[e] > vv[i1]) i1 = e;
        int i2 = -1;
        #pragma unroll
        for (int e = 0; e < E_ROUTED; e++) {
            if (e == i1) continue;
            if (i2 < 0 || vv[e] > vv[i2]) i2 = e;
        }
        float m = vv[i1], e1 = expf(vv[i1]-m), e2 = expf(vv[i2]-m), invs = 1.0f/(e1+e2);
        g_topidx[t*2+0] = i1; g_topidx[t*2+1] = i2;
        g_gate[t*2+0] = e1*invs; g_gate[t*2+1] = e2*invs;
    }
}

// ---------------- Transpose + fp16-convert (z-offset, 64x64 tiles) --------
__global__ void transpose_all(int zbase,
                              const float* __restrict__ W1, const float* __restrict__ W1s,
                              const float* __restrict__ W3, const float* __restrict__ W3s,
                              const float* __restrict__ W2, const float* __restrict__ W2s) {
    __shared__ float t[64][65];
    int z = zbase + blockIdx.z, which = z >> 3, e = z & 7;
    int R = (which < 2) ? DMODEL : DFF;
    int C = (which < 2) ? DFF : DMODEL;
    const float* rsrc = (which == 0) ? W1 : (which == 1) ? W3 : W2;
    const float* ssrc = (which == 0) ? W1s : (which == 1) ? W3s : W2s;
    const float* s = (e < E_ROUTED) ? rsrc + (size_t)e * WPER : ssrc;
    __half* d = ((which == 0) ? g_w1t : (which == 1) ? g_w3t : g_w2t) + (size_t)e * WPER;
    int rt = (which < 2) ? blockIdx.y : blockIdx.x;
    int ct = (which < 2) ? blockIdx.x : blockIdx.y;
    int tx = threadIdx.x & 63, ty = threadIdx.x >> 6;
    #pragma unroll
    for (int i = 0; i < 64; i += 4)
        t[ty + i][tx] = s[(size_t)(rt*64 + ty + i) * C + ct*64 + tx];
    __syncthreads();
    #pragma unroll
    for (int i = 0; i < 64; i += 4)
        d[(size_t)(ct*64 + ty + i) * R + rt*64 + tx] = __float2half(t[tx][ty + i]);
}

// ---------------- Dispatch positions ----------------
__global__ void pos_kernel() {
    int e = blockIdx.x;
    __shared__ int warpTot[8];
    int lane = threadIdx.x & 31, wid = threadIdx.x >> 5;
    int running = 0;
    for (int k = 0; k < TOPK; k++)
        for (int base = 0; base < T_TOK; base += 256) {
            int t = base + threadIdx.x;
            int match = (g_topidx[t*2+k] == e) ? 1 : 0;
            unsigned bal = __ballot_sync(0xffffffffu, match);
            int wpre = __popc(bal & ((1u << lane) - 1u));
            if (lane == 31) warpTot[wid] = wpre + match;
            __syncthreads();
            int wbase = 0;
            #pragma unroll
            for (int w = 0; w < 8; w++) if (w < wid) wbase += warpTot[w];
            if (match) {
                int p = running + wbase + wpre;
                if (p < CAPACITY) { g_pos[k*T_TOK+t] = p; g_slot_token[e*CAPACITY+p] = t; }
                else g_pos[k*T_TOK+t] = -1;
            }
            int tot = 0;
            #pragma unroll
            for (int w = 0; w < 8; w++) tot += warpTot[w];
            running += tot;
            __syncthreads();
        }
    if (threadIdx.x == 0) g_count[e] = (running < CAPACITY) ? running : CAPACITY;
}

// ================= Fused W1+W3 fp16 mma GEMM + SwiGLU (R15/R16 exact) ======
#define LDH 40
#define G13_A_B   (128*LDH*2)
#define G13_B1_O  G13_A_B
#define G13_B3_O  (G13_A_B + 64*LDH*2)
#define G13_STGB  (G13_A_B + 2*64*LDH*2)
#define G13_SMEM  (5 * G13_STGB)

__global__ void __launch_bounds__(256, 2) gemm13_mma() {
    extern __shared__ char smB[];
    const int e = blockIdx.z;
    const int n0 = blockIdx.x * 64;
    const int m0 = blockIdx.y * 128;
    const int cnt = (e < E_ROUTED) ? g_count[e] : T_TOK;
    if (m0 >= cnt) return;
    const int tid = threadIdx.x, wid = tid >> 5, lane = tid & 31;
    const int wm = wid >> 1, wn = wid & 1;
    const int gid = lane >> 2, t4 = lane & 3;

    const __half* w1e = g_w1t + (size_t)e * WPER;
    const __half* w3e = g_w3t + (size_t)e * WPER;

    const __half* agh[2]; uint32_t aoffB[2];
    #pragma unroll
    for (int i = 0; i < 2; i++) {
        int idx = tid + i*256;
        int r = idx >> 2, c = idx & 3;
        int mg = m0 + r;
        int tok = (e < E_ROUTED) ? ((mg < cnt) ? g_slot_token[e*CAPACITY + mg] : 0) : mg;
        agh[i] = g_ht + (size_t)tok * DMODEL + c*8;
        aoffB[i] = (uint32_t)(r*80 + c*16);
    }
    const __half* b1gh; const __half* b3gh; uint32_t boffB;
    {
        int n = tid >> 2, c = tid & 3;
        b1gh = w1e + (size_t)(n0 + n) * DMODEL + c*8;
        b3gh = w3e + (size_t)(n0 + n) * DMODEL + c*8;
        boffB = (uint32_t)(n*80 + c*16);
    }
    const uint32_t sbase = smem_u32(smB);

    float c1[2][4][4] = {};
    float c3[2][4][4] = {};

    auto load_stage = [&](int s, int j) {
        uint32_t st = sbase + (uint32_t)s * G13_STGB;
        cp16(st + aoffB[0], agh[0] + j*32);
        cp16(st + aoffB[1], agh[1] + j*32);
        cp16(st + G13_B1_O + boffB, b1gh + j*32);
        cp16(st + G13_B3_O + boffB, b3gh + j*32);
        cp_commit();
    };
    auto compute = [&](int s) {
        const char* stage = smB + s * G13_STGB;
        const uint32_t* A  = (const uint32_t*)(stage) + (wm*32)*20;
        const uint32_t* B1 = (const uint32_t*)(stage + G13_B1_O) + (wn*32)*20;
        const uint32_t* B3 = (const uint32_t*)(stage + G13_B3_O) + (wn*32)*20;
        #pragma unroll
        for (int ks = 0; ks < 2; ks++) {
            const int kb = ks*8 + t4;
            uint32_t a[2][4];
            #pragma unroll
            for (int t = 0; t < 2; t++) {
                int r = t*16 + gid;
                a[t][0] = A[r*20 + kb];
                a[t][1] = A[(r+8)*20 + kb];
                a[t][2] = A[r*20 + kb + 4];
                a[t][3] = A[(r+8)*20 + kb + 4];
            }
            #pragma unroll
            for (int u = 0; u < 4; u++) {
                const int nr = (u*8 + gid)*20;
                uint32_t p0 = B1[nr + kb], p1 = B1[nr + kb + 4];
                uint32_t q0 = B3[nr + kb], q1 = B3[nr + kb + 4];
                #pragma unroll
                for (int t = 0; t < 2; t++) {
                    mma_f16(c1[t][u], a[t][0], a[t][1], a[t][2], a[t][3], p0, p1);
                    mma_f16(c3[t][u], a[t][0], a[t][1], a[t][2], a[t][3], q0, q1);
                }
            }
        }
    };

    const int nch = DMODEL/32;
    load_stage(0, 0); load_stage(1, 1); load_stage(2, 2);
    int s = 0;
    #pragma unroll 1
    for (int j = 0; j < nch; j += 2) {
        if (j < nch - 2) cp_wait<1>();
        else             cp_wait<0>();   // TAIL pair
        __syncthreads();
        int s1 = s + 1; if (s1 >= 5) s1 -= 5;
        compute(s);
        compute(s1);
        if (j + 3 < nch) { int s3 = s + 3; if (s3 >= 5) s3 -= 5; load_stage(s3, j + 3); }
        if (j + 4 < nch) { int s4 = s + 4; if (s4 >= 5) s4 -= 5; load_stage(s4, j + 4); }
        s += 2; if (s >= 5) s -= 5;
    }

    __half* dstb = (e < E_ROUTED) ? g_ub + (size_t)e * CAPACITY * DFF : g_ubs;
    #pragma unroll
    for (int t = 0; t < 2; t++)
        #pragma unroll
        for (int half = 0; half < 2; half++) {
            int r = m0 + wm*32 + t*16 + gid + half*8;
            if (r < cnt) {
                __half* drow = dstb + (size_t)r * DFF + n0 + wn*32 + t4*2;
                #pragma unroll
                for (int u = 0; u < 4; u++) {
                    int ci = half*2;
                    float ux = silu_f(c1[t][u][ci])   * c3[t][u][ci];
                    float uy = silu_f(c1[t][u][ci+1]) * c3[t][u][ci+1];
                    *reinterpret_cast<__half2*>(drow + u*8) = __floats2half2_rn(ux, uy);
                }
            }
        }
}

// ================= W2 fp16 mma GEMM (fp16 output) =================
#define G2_A_B  (128*LDH*2)
#define G2_B_O  G2_A_B
#define G2_STGB (2 * G2_A_B)
#define G2_SMEM (5 * G2_STGB)

__global__ void __launch_bounds__(256, 2) gemm2_mma() {
    extern __shared__ char smB[];
    const int e = blockIdx.z;
    const int n0 = blockIdx.x * 128;
    const int m0 = blockIdx.y * 128;
    const int cnt = (e < E_ROUTED) ? g_count[e] : T_TOK;
    if (m0 >= cnt) return;
    const int tid = threadIdx.x, wid = tid >> 5, lane = tid & 31;
    const int wm = wid >> 1, wn = wid & 1;
    const int gid = lane >> 2, t4 = lane & 3;

    const __half* Abase = (e < E_ROUTED) ? g_ub + (size_t)e * CAPACITY * DFF : g_ubs;
    const __half* w2e = g_w2t + (size_t)e * WPER;

    const __half* agh[2]; uint32_t aoffB[2];
    #pragma unroll
    for (int i = 0; i < 2; i++) {
        int idx = tid + i*256;
        int r = idx >> 2, c = idx & 3;
        int mg = m0 + r;
        agh[i] = Abase + (size_t)((mg < cnt) ? mg : 0) * DFF + c*8;
        aoffB[i] = (uint32_t)(r*80 + c*16);
    }
    const __half* bgh[2]; uint32_t boffB[2];
    #pragma unroll
    for (int i = 0; i < 2; i++) {
        int idx = tid + i*256;
        int n = idx >> 2, c = idx & 3;
        bgh[i] = w2e + (size_t)(n0 + n) * DFF + c*8;
        boffB[i] = (uint32_t)(n*80 + c*16);
    }
    const uint32_t sbase = smem_u32(smB);

    float cc[2][8][4] = {};

    auto load_stage = [&](int s, int j) {
        uint32_t st = sbase + (uint32_t)s * G2_STGB;
        cp16(st + aoffB[0], agh[0] + j*32);
        cp16(st + aoffB[1], agh[1] + j*32);
        cp16(st + G2_B_O + boffB[0], bgh[0] + j*32);
        cp16(st + G2_B_O + boffB[1], bgh[1] + j*32);
        cp_commit();
    };
    auto compute = [&](int s) {
        const char* stage = smB + s * G2_STGB;
        const uint32_t* A = (const uint32_t*)(stage) + (wm*32)*20;
        const uint32_t* B = (const uint32_t*)(stage + G2_B_O) + (wn*64)*20;
        #pragma unroll
        for (int ks = 0; ks < 2; ks++) {
            const int kb = ks*8 + t4;
            uint32_t a[2][4];
            #pragma unroll
            for (int t = 0; t < 2; t++) {
                int r = t*16 + gid;
                a[t][0] = A[r*20 + kb];
                a[t][1] = A[(r+8)*20 + kb];
                a[t][2] = A[r*20 + kb + 4];
                a[t][3] = A[(r+8)*20 + kb + 4];
            }
            #pragma unroll
            for (int u = 0; u < 8; u++) {
                const int nr = (u*8 + gid)*20;
                uint32_t b0 = B[nr + kb], b1 = B[nr + kb + 4];
                #pragma unroll
                for (int t = 0; t < 2; t++)
                    mma_f16(cc[t][u], a[t][0], a[t][1], a[t][2], a[t][3], b0, b1);
            }
        }
    };

    const int nch = DFF/32;
    load_stage(0, 0); load_stage(1, 1); load_stage(2, 2);
    int s = 0;
    #pragma unroll 1
    for (int j = 0; j < nch; j += 2) {
        if (j < nch - 2) cp_wait<1>();
        else             cp_wait<0>();   // TAIL pair
        __syncthreads();
        int s1 = s + 1; if (s1 >= 5) s1 -= 5;
        compute(s);
        compute(s1);
        if (j + 3 < nch) { int s3 = s + 3; if (s3 >= 5) s3 -= 5; load_stage(s3, j + 3); }
        if (j + 4 < nch) { int s4 = s + 4; if (s4 >= 5) s4 -= 5; load_stage(s4, j + 4); }
        s += 2; if (s >= 5) s -= 5;
    }

    __half* dstb = (e < E_ROUTED) ? g_ye + (size_t)e * CAPACITY * DMODEL : g_ys;
    #pragma unroll
    for (int t = 0; t < 2; t++)
        #pragma unroll
        for (int half = 0; half < 2; half++) {
            int r = m0 + wm*32 + t*16 + gid + half*8;
            if (r < cnt) {
                __half* drow = dstb + (size_t)r * DMODEL + n0 + wn*64 + t4*2;
                #pragma unroll
                for (int u = 0; u < 8; u++) {
                    int ci = half*2;
                    *reinterpret_cast<__half2*>(drow + u*8) =
                        __floats2half2_rn(cc[t][u][ci], cc[t][u][ci+1]);
                }
            }
        }
}

// ---------------- Combine (fp16 inputs) ----------------
__global__ void combine_kernel(float* __restrict__ out) {
    int t = blockIdx.x, d4 = threadIdx.x;
    const __half2* ys2 = reinterpret_cast<const __half2*>(g_ys + (size_t)t * DMODEL);
    float2 s0 = __half22float2(ys2[d4*2+0]);
    float2 s1 = __half22float2(ys2[d4*2+1]);
    float4 o;
    o.x = s0.x; o.y = s0.y; o.z = s1.x; o.w = s1.y;
    #pragma unroll
    for (int k = 0; k < TOPK; k++) {
        int p = g_pos[k * T_TOK + t];
        if (p >= 0) {
            int e = g_topidx[t*2+k];
            float gv = g_gate[t*2+k];
            const __half2* y2 = reinterpret_cast<const __half2*>(
                g_ye + ((size_t)e*CAPACITY + p) * DMODEL);
            float2 y0 = __half22float2(y2[d4*2+0]);
            float2 y1 = __half22float2(y2[d4*2+1]);
            o.x += gv*y0.x; o.y += gv*y0.y; o.z += gv*y1.x; o.w += gv*y1.y;
        }
    }
    reinterpret_cast<float4*>(out + (size_t)t * DMODEL)[d4] = o;
}

// ---------------- launch (fork/join graph) ----------------
extern "C" void kernel_launch(void* const* d_in, const int* in_sizes, int n_in,
                              void* d_out, int out_size) {
    (void)in_sizes; (void)n_in; (void)out_size;
    const float* x    = (const float*)d_in[0];
    const float* ln_g = (const float*)d_in[1];
    const float* ln_b = (const float*)d_in[2];
    const float* Wr   = (const float*)d_in[3];
    const float* W1   = (const float*)d_in[4];
    const float* W3   = (const float*)d_in[5];
    const float* W2   = (const float*)d_in[6];
    const float* W1s  = (const float*)d_in[7];
    const float* W3s  = (const float*)d_in[8];
    const float* W2s  = (const float*)d_in[9];
    float* out = (float*)d_out;

    static cudaStream_t sR = nullptr, sT = nullptr, sW = nullptr;
    static cudaEvent_t  e0 = nullptr, eR = nullptr, eT = nullptr, eW = nullptr;
    if (sR == nullptr) {
        cudaStreamCreateWithFlags(&sR, cudaStreamNonBlocking);
        cudaStreamCreateWithFlags(&sT, cudaStreamNonBlocking);
        cudaStreamCreateWithFlags(&sW, cudaStreamNonBlocking);
        cudaEventCreateWithFlags(&e0, cudaEventDisableTiming);
        cudaEventCreateWithFlags(&eR, cudaEventDisableTiming);
        cudaEventCreateWithFlags(&eT, cudaEventDisableTiming);
        cudaEventCreateWithFlags(&eW, cudaEventDisableTiming);
        cudaFuncSetAttribute(gemm13_mma, cudaFuncAttributeMaxDynamicSharedMemorySize, G13_SMEM);
        cudaFuncSetAttribute(gemm2_mma,  cudaFuncAttributeMaxDynamicSharedMemorySize, G2_SMEM);
    }

    cudaStream_t s0 = (cudaStream_t)0;   // the captured stream

    cudaEventRecord(e0, s0);
    cudaStreamWaitEvent(sR, e0, 0);
    cudaStreamWaitEvent(sT, e0, 0);
    cudaStreamWaitEvent(sW, e0, 0);

    // branch R: LN+router -> dispatch
    ln_router_kernel<<<T_TOK, 256, 0, sR>>>(x, ln_g, ln_b, Wr);
    pos_kernel<<<E_ROUTED, 256, 0, sR>>>();
    cudaEventRecord(eR, sR);

    // branch T: W1/W3 transpose (z 0..15)
    transpose_all<<<dim3(64, 16, 16), 256, 0, sT>>>(0, W1, W1s, W3, W3s, W2, W2s);
    cudaEventRecord(eT, sT);

    // branch W: W2 transpose (z 16..23) — only needed by gemm2, hides under gemm13
    transpose_all<<<dim3(64, 16, 8), 256, 0, sW>>>(16, W1, W1s, W3, W3s, W2, W2s);
    cudaEventRecord(eW, sW);

    cudaStreamWaitEvent(s0, eR, 0);
    cudaStreamWaitEvent(s0, eT, 0);
    gemm13_mma<<<dim3(DFF/64, T_TOK/128, E_ROUTED + 1), 256, G13_SMEM, s0>>>();

    cudaStreamWaitEvent(s0, eW, 0);
    gemm2_mma<<<dim3(DMODEL/128, T_TOK/128, E_ROUTED + 1), 256, G2_SMEM, s0>>>();

    combine_kernel<<<T_TOK, 256, 0, s0>>>(out);
}